// round 11
// baseline (speedup 1.0000x reference)
#include <cuda_runtime.h>
#include <cuda_bf16.h>
#include <cstdint>

#define NROWS 32768
#define BSZ   1024
#define AGN   32
#define IND   96
#define HDIM  64
#define NNHD  64
#define ATTD  32
#define NACTD 16
#define LDIM  16
#define DLAT  512

typedef unsigned long long u64;

// ---------------- scratch (device globals) ----------------
__device__ float g_z1[NROWS * NNHD];
__device__ float g_q[NROWS * NACTD];
__device__ float g_query[NROWS * ATTD];
__device__ float g_m1h[NROWS * NNHD];
__device__ float g_lat[BSZ * AGN * AGN * LDIM];   // [b][j][i][l]
__device__ float g_alpha[BSZ * AGN * AGN];        // RAW scores [b][j][i]
__device__ float g_bn_a[NNHD];
__device__ float g_bn_c[NNHD];
__device__ float g_p1[128 * NNHD];
__device__ float g_p2[128 * NNHD];

// ---------------- packed f32x2 helpers (k4) ----------------
__device__ __forceinline__ u64 pk2(float lo, float hi) {
    u64 r; asm("mov.b64 %0, {%1, %2};" : "=l"(r) : "f"(lo), "f"(hi)); return r;
}
__device__ __forceinline__ void upk2(float& lo, float& hi, u64 v) {
    asm("mov.b64 {%0, %1}, %2;" : "=f"(lo), "=f"(hi) : "l"(v));
}
__device__ __forceinline__ u64 fma2_(u64 a, u64 b, u64 c) {
    u64 d; asm("fma.rn.f32x2 %0, %1, %2, %3;" : "=l"(d) : "l"(a), "l"(b), "l"(c)); return d;
}
__device__ __forceinline__ void cload(float* dst, const float* __restrict__ src,
                                      int n4, int tid, int nthr) {
    float4* d = reinterpret_cast<float4*>(dst);
    const float4* s = reinterpret_cast<const float4*>(src);
    for (int i = tid; i < n4; i += nthr) d[i] = __ldg(s + i);
}
__device__ __forceinline__ float sigmoidf_(float x) {
    return __fdividef(1.f, 1.f + __expf(-x));
}

// ---------------- warp MMA plumbing ----------------
__device__ __forceinline__ uint32_t smem_u32(const void* p) {
    uint32_t a;
    asm("{ .reg .u64 t; cvta.to.shared.u64 t, %1; cvt.u32.u64 %0, t; }" : "=r"(a) : "l"(p));
    return a;
}
#define SWZ128(o) ((o) ^ (((o) >> 3) & 0x70))
__device__ __forceinline__ void ldsm_x4(uint32_t& r0, uint32_t& r1, uint32_t& r2, uint32_t& r3,
                                        uint32_t addr) {
    asm volatile("ldmatrix.sync.aligned.m8n8.x4.shared.b16 {%0,%1,%2,%3}, [%4];"
                 : "=r"(r0), "=r"(r1), "=r"(r2), "=r"(r3) : "r"(addr));
}
__device__ __forceinline__ void ldsm_x2(uint32_t& r0, uint32_t& r1, uint32_t addr) {
    asm volatile("ldmatrix.sync.aligned.m8n8.x2.shared.b16 {%0,%1}, [%2];"
                 : "=r"(r0), "=r"(r1) : "r"(addr));
}
__device__ __forceinline__ void mma16816(float* d, const uint32_t* a, uint32_t b0, uint32_t b1) {
    asm volatile(
        "mma.sync.aligned.m16n8k16.row.col.f32.bf16.bf16.f32 "
        "{%0,%1,%2,%3}, {%4,%5,%6,%7}, {%8,%9}, {%0,%1,%2,%3};"
        : "+f"(d[0]), "+f"(d[1]), "+f"(d[2]), "+f"(d[3])
        : "r"(a[0]), "r"(a[1]), "r"(a[2]), "r"(a[3]), "r"(b0), "r"(b1));
}
__device__ __forceinline__ void bf_split2(float a, float b, uint32_t& hi, uint32_t& lo) {
    __nv_bfloat16 ha = __float2bfloat16(a), hb = __float2bfloat16(b);
    float ra = a - __bfloat162float(ha);
    float rb = b - __bfloat162float(hb);
    __nv_bfloat162 H = __halves2bfloat162(ha, hb);
    __nv_bfloat162 L = __floats2bfloat162_rn(ra, rb);
    hi = *reinterpret_cast<uint32_t*>(&H);
    lo = *reinterpret_cast<uint32_t*>(&L);
}

template<int NKT, int NTS>
__device__ __forceinline__ void mma_pass(float (&acc)[2][8][4],
    uint32_t aH, uint32_t aL, uint32_t bH, uint32_t bL, int w, int lane)
{
#pragma unroll
    for (int kt = 0; kt < NKT; kt++) {
        uint32_t ah[2][4], al[2][4];
#pragma unroll
        for (int mt = 0; mt < 2; mt++) {
            uint32_t aoff = SWZ128((uint32_t)(
                (w * 32 + mt * 16 + (lane & 15)) * 128 + kt * 32 + (lane >> 4) * 16));
            ldsm_x4(ah[mt][0], ah[mt][1], ah[mt][2], ah[mt][3], aH + aoff);
            ldsm_x4(al[mt][0], al[mt][1], al[mt][2], al[mt][3], aL + aoff);
        }
#pragma unroll
        for (int nt = 0; nt < NTS; nt++) {
            uint32_t boff = SWZ128((uint32_t)(
                (nt * 8 + (lane & 7)) * 128 + kt * 32 + ((lane >> 3) & 1) * 16));
            uint32_t bh0, bh1, bl0, bl1;
            ldsm_x2(bh0, bh1, bH + boff);
            ldsm_x2(bl0, bl1, bL + boff);
#pragma unroll
            for (int mt = 0; mt < 2; mt++) {
                mma16816(acc[mt][nt], ah[mt], bh0, bh1);
                mma16816(acc[mt][nt], ah[mt], bl0, bl1);
                mma16816(acc[mt][nt], al[mt], bh0, bh1);
            }
        }
    }
}

// build [64 n x 64 k] bf16 hi/lo SW128 B tile from row-major gmem
__device__ __forceinline__ void build_b64(char* hi, char* lo,
    const float* __restrict__ src, int stride, int tid)
{
#pragma unroll
    for (int k = 0; k < 8; k++) {
        int idx4 = tid + k * 128;
        int n = idx4 >> 4, c4 = idx4 & 15;
        float4 v = __ldg(reinterpret_cast<const float4*>(src + (size_t)n * stride + c4 * 4));
        uint32_t h0, l0, h1, l1;
        bf_split2(v.x, v.y, h0, l0);
        bf_split2(v.z, v.w, h1, l1);
        uint32_t off = SWZ128((uint32_t)(n * 128 + c4 * 8));
        *reinterpret_cast<uint2*>(hi + off) = make_uint2(h0, h1);
        *reinterpret_cast<uint2*>(lo + off) = make_uint2(l0, l1);
    }
}

__device__ __forceinline__ void init_acc(float (&acc)[2][8][4], const float* sBias, int e0)
{
#pragma unroll
    for (int mt = 0; mt < 2; mt++)
#pragma unroll
        for (int nt = 0; nt < 8; nt++) {
            float b0 = sBias[nt * 8 + e0], b1 = sBias[nt * 8 + e0 + 1];
            acc[mt][nt][0] = b0; acc[mt][nt][1] = b1;
            acc[mt][nt][2] = b0; acc[mt][nt][3] = b1;
        }
}

#define LGSCALE 0.721347520444482f
#define SQVF    0.044721359549996f

// ---------------- K1T: trunk on tensor cores ----------------
#define K1_XA_HI 0
#define K1_XA_LO 16384
#define K1_XB_HI 32768
#define K1_XB_LO 49152
#define K1_H_HI  65536
#define K1_H_LO  81920
#define K1_B0_HI 98304
#define K1_B0_LO 106496
#define K1_B1_HI 114688
#define K1_B1_LO 122880
#define K1_SR    131072
#define K1_SZ    164864
#define K1_SBIAS 198656
#define K1_SMEM  199168

__global__ void __launch_bounds__(128) k1t_trunk(
    const float* __restrict__ inp, const float* __restrict__ h0in,
    const float* __restrict__ fc1_w, const float* __restrict__ fc1_b,
    const float* __restrict__ wih, const float* __restrict__ whh,
    const float* __restrict__ bih, const float* __restrict__ bhh,
    const float* __restrict__ fc2_w, const float* __restrict__ fc2_b,
    const float* __restrict__ emb_w1, const float* __restrict__ emb_b1,
    const float* __restrict__ wq_w, const float* __restrict__ wq_b,
    const float* __restrict__ msg_w1, const float* __restrict__ msg_b1,
    float* __restrict__ h_out)
{
    extern __shared__ char sm[];
    const uint32_t sbase = smem_u32(sm);
    float* smf = reinterpret_cast<float*>(sm);
    float* sBias = smf + K1_SBIAS / 4;
    const int tid = threadIdx.x;
    const int w = tid >> 5;
    const int lane = tid & 31;
    const int e0 = 2 * (lane & 3);
    const int row0 = blockIdx.x * 128;
    const float qs = 0.17677669529663687f;

    // ---- A build ----
    {
        const float4* ip = reinterpret_cast<const float4*>(inp + (size_t)(row0 + tid) * IND);
#pragma unroll
        for (int k = 0; k < 24; k++) {
            float4 v = __ldg(ip + k);
            uint32_t hA, lA, hB, lB;
            bf_split2(v.x, v.y, hA, lA);
            bf_split2(v.z, v.w, hB, lB);
            if (k < 16) {
                uint32_t off = SWZ128((uint32_t)(tid * 128 + k * 8));
                *reinterpret_cast<uint2*>(sm + K1_XA_HI + off) = make_uint2(hA, hB);
                *reinterpret_cast<uint2*>(sm + K1_XA_LO + off) = make_uint2(lA, lB);
            } else {
                uint32_t off = SWZ128((uint32_t)(tid * 128 + (k - 16) * 8));
                *reinterpret_cast<uint2*>(sm + K1_XB_HI + off) = make_uint2(hA, hB);
                *reinterpret_cast<uint2*>(sm + K1_XB_LO + off) = make_uint2(lA, lB);
            }
        }
        const float4* hp = reinterpret_cast<const float4*>(h0in + (size_t)(row0 + tid) * HDIM);
#pragma unroll
        for (int k = 0; k < 16; k++) {
            float4 v = __ldg(hp + k);
            uint32_t hA, lA, hB, lB;
            bf_split2(v.x, v.y, hA, lA);
            bf_split2(v.z, v.w, hB, lB);
            uint32_t off = SWZ128((uint32_t)(tid * 128 + k * 8));
            *reinterpret_cast<uint2*>(sm + K1_H_HI + off) = make_uint2(hA, hB);
            *reinterpret_cast<uint2*>(sm + K1_H_LO + off) = make_uint2(lA, lB);
        }
    }
    build_b64(sm + K1_B0_HI, sm + K1_B0_LO, fc1_w, IND, tid);
#pragma unroll
    for (int k = 0; k < 4; k++) {
        int idx = tid + k * 128;
        int n = idx >> 3, c4 = idx & 7;
        float4 v = __ldg(reinterpret_cast<const float4*>(fc1_w + (size_t)n * IND + 64 + c4 * 4));
        uint32_t h0_, l0_, h1_, l1_;
        bf_split2(v.x, v.y, h0_, l0_);
        bf_split2(v.z, v.w, h1_, l1_);
        uint32_t off = SWZ128((uint32_t)(n * 128 + c4 * 8));
        *reinterpret_cast<uint2*>(sm + K1_B1_HI + off) = make_uint2(h0_, h1_);
        *reinterpret_cast<uint2*>(sm + K1_B1_LO + off) = make_uint2(l0_, l1_);
    }
    if (tid < 64) sBias[tid] = __ldg(fc1_b + tid);
    __syncthreads();

    float acc[2][8][4];

    // ---- fc1 GEMM + relu -> x tile ----
    init_acc(acc, sBias, e0);
    mma_pass<4, 8>(acc, sbase + K1_XA_HI, sbase + K1_XA_LO, sbase + K1_B0_HI, sbase + K1_B0_LO, w, lane);
    mma_pass<2, 8>(acc, sbase + K1_XB_HI, sbase + K1_XB_LO, sbase + K1_B1_HI, sbase + K1_B1_LO, w, lane);
#pragma unroll
    for (int mt = 0; mt < 2; mt++)
#pragma unroll
        for (int h01 = 0; h01 < 2; h01++) {
            int row = w * 32 + mt * 16 + (lane >> 2) + 8 * h01;
#pragma unroll
            for (int nt = 0; nt < 8; nt++) {
                int c = nt * 8 + e0;
                float v0 = fmaxf(acc[mt][nt][h01 * 2 + 0], 0.f);
                float v1 = fmaxf(acc[mt][nt][h01 * 2 + 1], 0.f);
                uint32_t hh, ll;
                bf_split2(v0, v1, hh, ll);
                uint32_t off = SWZ128((uint32_t)(row * 128 + c * 2));
                *reinterpret_cast<uint32_t*>(sm + K1_XA_HI + off) = hh;
                *reinterpret_cast<uint32_t*>(sm + K1_XA_LO + off) = ll;
            }
        }
    __syncthreads();

    // ---- GRU r gate ----
    build_b64(sm + K1_B0_HI, sm + K1_B0_LO, wih, HDIM, tid);
    build_b64(sm + K1_B1_HI, sm + K1_B1_LO, whh, HDIM, tid);
    if (tid < 64) sBias[tid] = __ldg(bih + tid) + __ldg(bhh + tid);
    __syncthreads();
    init_acc(acc, sBias, e0);
    mma_pass<4, 8>(acc, sbase + K1_XA_HI, sbase + K1_XA_LO, sbase + K1_B0_HI, sbase + K1_B0_LO, w, lane);
    mma_pass<4, 8>(acc, sbase + K1_H_HI,  sbase + K1_H_LO,  sbase + K1_B1_HI, sbase + K1_B1_LO, w, lane);
#pragma unroll
    for (int mt = 0; mt < 2; mt++)
#pragma unroll
        for (int h01 = 0; h01 < 2; h01++) {
            int row = w * 32 + mt * 16 + (lane >> 2) + 8 * h01;
#pragma unroll
            for (int nt = 0; nt < 8; nt++) {
                int c = nt * 8 + e0;
                *reinterpret_cast<float2*>(smf + K1_SR / 4 + row * 66 + c) =
                    make_float2(sigmoidf_(acc[mt][nt][h01 * 2 + 0]),
                                sigmoidf_(acc[mt][nt][h01 * 2 + 1]));
            }
        }
    __syncthreads();

    // ---- GRU z gate ----
    build_b64(sm + K1_B0_HI, sm + K1_B0_LO, wih + 64 * HDIM, HDIM, tid);
    build_b64(sm + K1_B1_HI, sm + K1_B1_LO, whh + 64 * HDIM, HDIM, tid);
    if (tid < 64) sBias[tid] = __ldg(bih + 64 + tid) + __ldg(bhh + 64 + tid);
    __syncthreads();
    init_acc(acc, sBias, e0);
    mma_pass<4, 8>(acc, sbase + K1_XA_HI, sbase + K1_XA_LO, sbase + K1_B0_HI, sbase + K1_B0_LO, w, lane);
    mma_pass<4, 8>(acc, sbase + K1_H_HI,  sbase + K1_H_LO,  sbase + K1_B1_HI, sbase + K1_B1_LO, w, lane);
#pragma unroll
    for (int mt = 0; mt < 2; mt++)
#pragma unroll
        for (int h01 = 0; h01 < 2; h01++) {
            int row = w * 32 + mt * 16 + (lane >> 2) + 8 * h01;
#pragma unroll
            for (int nt = 0; nt < 8; nt++) {
                int c = nt * 8 + e0;
                *reinterpret_cast<float2*>(smf + K1_SZ / 4 + row * 66 + c) =
                    make_float2(sigmoidf_(acc[mt][nt][h01 * 2 + 0]),
                                sigmoidf_(acc[mt][nt][h01 * 2 + 1]));
            }
        }
    __syncthreads();

    // ---- GRU n gate ----
    build_b64(sm + K1_B0_HI, sm + K1_B0_LO, wih + 128 * HDIM, HDIM, tid);
    build_b64(sm + K1_B1_HI, sm + K1_B1_LO, whh + 128 * HDIM, HDIM, tid);
    if (tid < 64) sBias[tid] = __ldg(bih + 128 + tid);
    else sBias[tid] = __ldg(bhh + 128 + (tid - 64));
    __syncthreads();
    float acc2[2][8][4];
    init_acc(acc, sBias, e0);
    init_acc(acc2, sBias + 64, e0);
    mma_pass<4, 8>(acc,  sbase + K1_XA_HI, sbase + K1_XA_LO, sbase + K1_B0_HI, sbase + K1_B0_LO, w, lane);
    mma_pass<4, 8>(acc2, sbase + K1_H_HI,  sbase + K1_H_LO,  sbase + K1_B1_HI, sbase + K1_B1_LO, w, lane);

    // ---- blend ----
#pragma unroll
    for (int mt = 0; mt < 2; mt++)
#pragma unroll
        for (int h01 = 0; h01 < 2; h01++) {
            int row = w * 32 + mt * 16 + (lane >> 2) + 8 * h01;
            int grow = row0 + row;
#pragma unroll
            for (int nt = 0; nt < 8; nt++) {
                int c = nt * 8 + e0;
                float2 rv = *reinterpret_cast<const float2*>(smf + K1_SR / 4 + row * 66 + c);
                float2 zv = *reinterpret_cast<const float2*>(smf + K1_SZ / 4 + row * 66 + c);
                float n0 = tanhf(acc[mt][nt][h01 * 2 + 0] + rv.x * acc2[mt][nt][h01 * 2 + 0]);
                float n1 = tanhf(acc[mt][nt][h01 * 2 + 1] + rv.y * acc2[mt][nt][h01 * 2 + 1]);
                float2 h0v = __ldg(reinterpret_cast<const float2*>(h0in + (size_t)grow * HDIM + c));
                float hn0 = (1.f - zv.x) * n0 + zv.x * h0v.x;
                float hn1 = (1.f - zv.y) * n1 + zv.y * h0v.y;
                *reinterpret_cast<float2*>(h_out + (size_t)grow * HDIM + c) = make_float2(hn0, hn1);
                uint32_t hh, ll;
                bf_split2(hn0, hn1, hh, ll);
                uint32_t off = SWZ128((uint32_t)(row * 128 + c * 2));
                *reinterpret_cast<uint32_t*>(sm + K1_H_HI + off) = hh;
                *reinterpret_cast<uint32_t*>(sm + K1_H_LO + off) = ll;
            }
        }
    __syncthreads();

    // ---- heads ----
#pragma unroll
    for (int p = 0; p < 3; p++) {
        const int rows = (p == 2) ? 48 : 64;
#pragma unroll
        for (int k = 0; k < 8; k++) {
            int idx4 = tid + k * 128;
            int n = idx4 >> 4, c4 = idx4 & 15;
            if (n < rows) {
                int g = p * 64 + n;
                const float* src; float sc = 1.f;
                if (g < 16)       src = fc2_w + (size_t)g * HDIM;
                else if (g < 80)  src = emb_w1 + (size_t)(g - 16) * HDIM;
                else if (g < 112) { src = wq_w + (size_t)(g - 80) * HDIM; sc = qs; }
                else              src = msg_w1 + (size_t)(g - 112) * 80;
                float4 v = __ldg(reinterpret_cast<const float4*>(src + c4 * 4));
                uint32_t h0_, l0_, h1_, l1_;
                bf_split2(v.x * sc, v.y * sc, h0_, l0_);
                bf_split2(v.z * sc, v.w * sc, h1_, l1_);
                uint32_t off = SWZ128((uint32_t)(n * 128 + c4 * 8));
                *reinterpret_cast<uint2*>(sm + K1_B0_HI + off) = make_uint2(h0_, h1_);
                *reinterpret_cast<uint2*>(sm + K1_B0_LO + off) = make_uint2(l0_, l1_);
            }
        }
        if (tid < rows) {
            int g = p * 64 + tid; float bv;
            if (g < 16)       bv = __ldg(fc2_b + g);
            else if (g < 80)  bv = __ldg(emb_b1 + g - 16);
            else if (g < 112) bv = __ldg(wq_b + g - 80) * qs;
            else              bv = __ldg(msg_b1 + g - 112);
            sBias[tid] = bv;
        }
        __syncthreads();
        init_acc(acc, sBias, e0);
        if (p == 2)
            mma_pass<4, 6>(acc, sbase + K1_H_HI, sbase + K1_H_LO, sbase + K1_B0_HI, sbase + K1_B0_LO, w, lane);
        else
            mma_pass<4, 8>(acc, sbase + K1_H_HI, sbase + K1_H_LO, sbase + K1_B0_HI, sbase + K1_B0_LO, w, lane);
        const int nts = (p == 2) ? 6 : 8;
#pragma unroll
        for (int mt = 0; mt < 2; mt++)
#pragma unroll
            for (int h01 = 0; h01 < 2; h01++) {
                int row = w * 32 + mt * 16 + (lane >> 2) + 8 * h01;
                int grow = row0 + row;
                for (int nt = 0; nt < nts; nt++) {
                    int cg = p * 64 + nt * 8 + e0;
                    float v0 = acc[mt][nt][h01 * 2 + 0];
                    float v1 = acc[mt][nt][h01 * 2 + 1];
                    float* dst;
                    if (cg < 16)       dst = g_q + (size_t)grow * NACTD + cg;
                    else if (cg < 80)  dst = g_z1 + (size_t)grow * NNHD + (cg - 16);
                    else if (cg < 112) dst = g_query + (size_t)grow * ATTD + (cg - 80);
                    else               dst = g_m1h + (size_t)grow * NNHD + (cg - 112);
                    *reinterpret_cast<float2*>(dst) = make_float2(v0, v1);
                }
            }
        __syncthreads();
    }
}

// ---------------- K2a/K2b: BN statistics ----------------
__global__ void __launch_bounds__(256) k2a_bn()
{
    __shared__ float ss[4][NNHD], sq[4][NNHD];
    const int tid = threadIdx.x;
    const int f = tid & 63;
    const int rg = tid >> 6;
    const int base = blockIdx.x * 256;
    float s0 = 0.f, q0 = 0.f, s1 = 0.f, q1 = 0.f;
    float s2 = 0.f, q2 = 0.f, s3 = 0.f, q3 = 0.f;
    // 4 independent load chains (MLP=4)
    for (int r = rg; r < 256; r += 16) {
        float v0 = g_z1[(size_t)(base + r) * NNHD + f];
        float v1 = g_z1[(size_t)(base + r + 4) * NNHD + f];
        float v2 = g_z1[(size_t)(base + r + 8) * NNHD + f];
        float v3 = g_z1[(size_t)(base + r + 12) * NNHD + f];
        s0 += v0; q0 = fmaf(v0, v0, q0);
        s1 += v1; q1 = fmaf(v1, v1, q1);
        s2 += v2; q2 = fmaf(v2, v2, q2);
        s3 += v3; q3 = fmaf(v3, v3, q3);
    }
    ss[rg][f] = (s0 + s1) + (s2 + s3);
    sq[rg][f] = (q0 + q1) + (q2 + q3);
    __syncthreads();
    if (tid < NNHD) {
        g_p1[blockIdx.x * NNHD + tid] = ss[0][tid] + ss[1][tid] + ss[2][tid] + ss[3][tid];
        g_p2[blockIdx.x * NNHD + tid] = sq[0][tid] + sq[1][tid] + sq[2][tid] + sq[3][tid];
    }
}
__global__ void __launch_bounds__(256) k2b_bn(const float* __restrict__ bn_g,
                                              const float* __restrict__ bn_b)
{
    __shared__ float ss[256], sq[256];
    const int tid = threadIdx.x;
    const int f = tid & 63;
    const int rg = tid >> 6;
    float s = 0.f, q = 0.f;
#pragma unroll
    for (int i = rg; i < 128; i += 4) {
        s += g_p1[i * NNHD + f];
        q += g_p2[i * NNHD + f];
    }
    ss[tid] = s; sq[tid] = q;
    __syncthreads();
    if (tid < NNHD) {
        float S = ss[f] + ss[64 + f] + ss[128 + f] + ss[192 + f];
        float Q = sq[f] + sq[64 + f] + sq[128 + f] + sq[192 + f];
        float mean = S * (1.f / (float)NROWS);
        float var  = Q * (1.f / (float)NROWS) - mean * mean;
        float a = __ldg(bn_g + f) / sqrtf(var + 1e-5f);
        g_bn_a[f] = a;
        g_bn_c[f] = __ldg(bn_b + f) - a * mean;
    }
}

// ---------------- K3m: latent GEMM, t-chunks split across blockIdx.y ----------------
#define K3M_SA_HI 0
#define K3M_SA_LO 16384
#define K3M_SB_HI 32768
#define K3M_SB_LO 49152
#define K3M_SQK   65536
#define K3M_SQB   73728
#define K3M_SWK   74240
#define K3M_SBIAS 76288
#define K3M_SMEM  76800

__global__ void __launch_bounds__(128) k3m_latent(
    const float* __restrict__ eps,
    const float* __restrict__ emb_w2, const float* __restrict__ emb_b2,
    const float* __restrict__ wk_w, const float* __restrict__ wk_b)
{
    extern __shared__ char sm[];
    const uint32_t sbase = smem_u32(sm);
    float* smf = reinterpret_cast<float*>(sm);
    const int tid = threadIdx.x;
    const int w = tid >> 5;
    const int lane = tid & 31;
    const int row0 = blockIdx.x * 128;
    const int b = blockIdx.x * 4 + w;
    const int e0 = 2 * (lane & 3);

    {
        const float4* zpg = reinterpret_cast<const float4*>(g_z1 + (size_t)(row0 + tid) * NNHD);
#pragma unroll
        for (int k = 0; k < 16; k++) {
            float4 v = __ldg(zpg + k);
            float t0 = g_bn_a[4*k+0] * v.x + g_bn_c[4*k+0]; t0 = t0 > 0.f ? t0 : 0.01f * t0;
            float t1 = g_bn_a[4*k+1] * v.y + g_bn_c[4*k+1]; t1 = t1 > 0.f ? t1 : 0.01f * t1;
            float t2 = g_bn_a[4*k+2] * v.z + g_bn_c[4*k+2]; t2 = t2 > 0.f ? t2 : 0.01f * t2;
            float t3 = g_bn_a[4*k+3] * v.w + g_bn_c[4*k+3]; t3 = t3 > 0.f ? t3 : 0.01f * t3;
            uint32_t h0, l0, h1, l1;
            bf_split2(t0, t1, h0, l0);
            bf_split2(t2, t3, h1, l1);
            uint32_t off = SWZ128((uint32_t)(tid * 128 + k * 8));
            *reinterpret_cast<uint2*>(sm + K3M_SA_HI + off) = make_uint2(h0, h1);
            *reinterpret_cast<uint2*>(sm + K3M_SA_LO + off) = make_uint2(l0, l1);
        }
    }
    cload(smf + K3M_SWK / 4, wk_w, 128, tid, 128);
    __syncthreads();

    {
        const float* swk = smf + K3M_SWK / 4;
        float qk[16];
#pragma unroll
        for (int l = 0; l < 16; l++) qk[l] = 0.f;
        float qb = 0.f;
        const float4* qp = reinterpret_cast<const float4*>(g_query + (size_t)(row0 + tid) * ATTD);
#pragma unroll
        for (int k = 0; k < 8; k++) {
            float4 v = __ldg(qp + k);
            float qa[4] = {v.x, v.y, v.z, v.w};
#pragma unroll
            for (int u = 0; u < 4; u++) {
                int a = 4*k + u;
#pragma unroll
                for (int l = 0; l < 16; l++) qk[l] = fmaf(qa[u], swk[a*16 + l], qk[l]);
                qb = fmaf(qa[u], __ldg(wk_b + a), qb);
            }
        }
#pragma unroll
        for (int l = 0; l < 16; l++) smf[K3M_SQK / 4 + tid * 16 + l] = qk[l];
        smf[K3M_SQB / 4 + tid] = qb;
    }
    __syncthreads();

    float qkr[4][4], qbr[4];
#pragma unroll
    for (int rr = 0; rr < 4; rr++) {
        int rloc = w * 32 + ((rr >> 1) ? 16 : 0) + (lane >> 2) + ((rr & 1) ? 8 : 0);
        const float* q = smf + K3M_SQK / 4 + rloc * 16;
        qkr[rr][0] = q[e0]; qkr[rr][1] = q[e0 + 1];
        qkr[rr][2] = q[e0 + 8]; qkr[rr][3] = q[e0 + 9];
        qbr[rr] = smf[K3M_SQB / 4 + rloc];
    }

    for (int tt = 0; tt < 4; tt++) {
        const int t = blockIdx.y * 4 + tt;
        if (tt > 0) __syncthreads();
#pragma unroll
        for (int k = 0; k < 16; k++) {
            int idx4 = tid + k * 128;
            int n = idx4 >> 4, c4 = idx4 & 15;
            int h = n >> 6, q = (n >> 5) & 1;
            int dl = 32 * h + (n & 31);
            int wrow = (q ? 512 : 0) + 64 * t + dl;
            float sc = q ? LGSCALE : 1.f;
            float4 v = __ldg(reinterpret_cast<const float4*>(emb_w2 + wrow * 64 + c4 * 4));
            uint32_t h0, l0, h1, l1;
            bf_split2(v.x * sc, v.y * sc, h0, l0);
            bf_split2(v.z * sc, v.w * sc, h1, l1);
            uint32_t off = SWZ128((uint32_t)(n * 128 + c4 * 8));
            *reinterpret_cast<uint2*>(sm + K3M_SB_HI + off) = make_uint2(h0, h1);
            *reinterpret_cast<uint2*>(sm + K3M_SB_LO + off) = make_uint2(l0, l1);
        }
        {
            int n = tid;
            int h = n >> 6, q = (n >> 5) & 1;
            int dl = 32 * h + (n & 31);
            float bv = __ldg(emb_b2 + (q ? 512 : 0) + 64 * t + dl);
            smf[K3M_SBIAS / 4 + n] = q ? bv * LGSCALE : bv;
        }
        __syncthreads();

        for (int hh = 0; hh < 2; hh++) {
            const int nbase = hh * 64;
            float acc[2][8][4];
#pragma unroll
            for (int mt = 0; mt < 2; mt++)
#pragma unroll
                for (int nt = 0; nt < 8; nt++) {
                    float b0 = smf[K3M_SBIAS / 4 + nbase + nt * 8 + e0];
                    float b1 = smf[K3M_SBIAS / 4 + nbase + nt * 8 + e0 + 1];
                    acc[mt][nt][0] = b0; acc[mt][nt][1] = b1;
                    acc[mt][nt][2] = b0; acc[mt][nt][3] = b1;
                }
#pragma unroll
            for (int kt = 0; kt < 4; kt++) {
                uint32_t ah[2][4], al[2][4];
#pragma unroll
                for (int mt = 0; mt < 2; mt++) {
                    uint32_t aoff = SWZ128((uint32_t)(
                        (w * 32 + mt * 16 + (lane & 15)) * 128 + kt * 32 + (lane >> 4) * 16));
                    ldsm_x4(ah[mt][0], ah[mt][1], ah[mt][2], ah[mt][3], sbase + K3M_SA_HI + aoff);
                    ldsm_x4(al[mt][0], al[mt][1], al[mt][2], al[mt][3], sbase + K3M_SA_LO + aoff);
                }
#pragma unroll
                for (int nt = 0; nt < 8; nt++) {
                    uint32_t boff = SWZ128((uint32_t)(
                        (nbase + nt * 8 + (lane & 7)) * 128 + kt * 32 + ((lane >> 3) & 1) * 16));
                    uint32_t bh0, bh1, bl0, bl1;
                    ldsm_x2(bh0, bh1, sbase + K3M_SB_HI + boff);
                    ldsm_x2(bl0, bl1, sbase + K3M_SB_LO + boff);
#pragma unroll
                    for (int mt = 0; mt < 2; mt++) {
                        mma16816(acc[mt][nt], ah[mt], bh0, bh1);
                        mma16816(acc[mt][nt], ah[mt], bl0, bl1);
                        mma16816(acc[mt][nt], al[mt], bh0, bh1);
                    }
                }
            }
#pragma unroll
            for (int mt = 0; mt < 2; mt++) {
#pragma unroll
                for (int h01 = 0; h01 < 2; h01++) {
                    const int rloc = w * 32 + mt * 16 + (lane >> 2) + 8 * h01;
                    const int rr = mt * 2 + h01;
                    const int i = rloc & 31;
                    float ap0 = 0.f, ap1 = 0.f;
#pragma unroll
                    for (int nt = 0; nt < 4; nt++) {
                        const int c = nt * 8 + e0;
                        float mu0 = acc[mt][nt][h01*2+0];
                        float mu1 = acc[mt][nt][h01*2+1];
                        float lg0 = acc[mt][nt+4][h01*2+0];
                        float lg1 = acc[mt][nt+4][h01*2+1];
                        float s0 = fmaxf(exp2f(lg0), SQVF);
                        float s1 = fmaxf(exp2f(lg1), SQVF);
                        const int dglob = t * 64 + 32 * hh + c;
                        float2 ev = __ldg(reinterpret_cast<const float2*>(
                            eps + (size_t)(row0 + rloc) * DLAT + dglob));
                        float l0 = fmaf(s0, ev.x, mu0);
                        float l1 = fmaf(s1, ev.y, mu1);
                        const int j = 4 * t + 2 * hh + (c >> 4);
                        const int pos = c & 15;
                        *reinterpret_cast<float2*>(
                            g_lat + (((size_t)(b * AGN + j)) * AGN + i) * LDIM + pos)
                            = make_float2(l0, l1);
                        float pa = qkr[rr][(nt & 1) * 2 + 0] * l0
                                 + qkr[rr][(nt & 1) * 2 + 1] * l1;
                        if (nt < 2) ap0 += pa; else ap1 += pa;
                    }
                    ap0 += __shfl_xor_sync(0xffffffffu, ap0, 1);
                    ap0 += __shfl_xor_sync(0xffffffffu, ap0, 2);
                    ap1 += __shfl_xor_sync(0xffffffffu, ap1, 1);
                    ap1 += __shfl_xor_sync(0xffffffffu, ap1, 2);
                    if ((lane & 3) == 0) {
                        int j0 = 4 * t + 2 * hh;
                        g_alpha[((size_t)(b * AGN + j0)) * AGN + i]     = ap0 + qbr[rr];
                        g_alpha[((size_t)(b * AGN + j0 + 1)) * AGN + i] = ap1 + qbr[rr];
                    }
                }
            }
        }
    }
}

// ---------------- K4: softmax + message MLP + aggregate (512 threads, 2 j per warp) ----------------
#define K4_SMEM ((16384 + 16 * 68 + 16 + 32 * 33 + 16 * 68) * 4)
__global__ void __launch_bounds__(512) k4_msg(
    const float* __restrict__ msg_w1,
    const float* __restrict__ msg_w2, const float* __restrict__ msg_b2,
    float* __restrict__ ret_q)
{
    extern __shared__ float sm4[];
    float* latS = sm4;
    float* sW2  = sm4 + 16384;
    float* sB2  = sW2 + 16 * 68;
    float* sal  = sB2 + 16;
    float* sU   = sal + 32 * 33;
    const int tid = threadIdx.x;
    const int w = tid >> 5;
    const int lane = tid & 31;
    const int b = blockIdx.x;

    {
        const float4* latg = reinterpret_cast<const float4*>(g_lat + (size_t)b * 16384);
        float4* latd = reinterpret_cast<float4*>(latS);
#pragma unroll
        for (int i = 0; i < 8; i++)
            latd[tid + i * 512] = __ldg(latg + tid + i * 512);
    }
    for (int idx = tid; idx < 16 * 64; idx += 512) {
        int rr = idx >> 6, cc = idx & 63;
        sW2[rr * 68 + cc] = __ldg(msg_w2 + idx);
    }
    if (tid < 16) sB2[tid] = __ldg(msg_b2 + tid);
    for (int idx = tid; idx < 1024; idx += 512) {
        int jj = idx >> 5, ii = idx & 31;
        sal[jj * 33 + ii] = g_alpha[(size_t)b * 1024 + idx];
    }

    u64 w1a[8], w1b[8];
    {
        const float4* p0 = reinterpret_cast<const float4*>(msg_w1 + lane * 80 + 64);
        const float4* p1 = reinterpret_cast<const float4*>(msg_w1 + (lane + 32) * 80 + 64);
#pragma unroll
        for (int k = 0; k < 4; k++) {
            float4 v0 = __ldg(p0 + k), v1 = __ldg(p1 + k);
            w1a[2*k] = pk2(v0.x, v0.y); w1a[2*k+1] = pk2(v0.z, v0.w);
            w1b[2*k] = pk2(v1.x, v1.y); w1b[2*k+1] = pk2(v1.z, v1.w);
        }
    }
    __syncthreads();

    if (tid < 32) {
        const int ii = tid;
        float m = -3.4e38f;
#pragma unroll
        for (int j = 0; j < AGN; j++) {
            float v = (j == ii) ? -1e9f : sal[j * 33 + ii];
            m = fmaxf(m, v);
        }
        float s = 0.f;
#pragma unroll
        for (int j = 0; j < AGN; j++) {
            float v = (j == ii) ? -1e9f : sal[j * 33 + ii];
            float e = expf(v - m);
            sal[j * 33 + ii] = e;
            s += e;
        }
        float inv = 1.f / s;
#pragma unroll
        for (int j = 0; j < AGN; j++) sal[j * 33 + ii] *= inv;
    }
    __syncthreads();

#pragma unroll
    for (int jj = 0; jj < 2; jj++) {
        const int j = w + jj * 16;
        const int bj = b * AGN + j;
        const float m0 = __ldg(g_m1h + (size_t)bj * NNHD + lane);
        const float m1 = __ldg(g_m1h + (size_t)bj * NNHD + 32 + lane);
        const float* latbase = latS + j * 512;
        const float* alb = sal + j * 33;
        float u0 = 0.f, u1 = 0.f, sa = 0.f;

        for (int i = 0; i < AGN; i++) {
            const ulonglong2* l2 = reinterpret_cast<const ulonglong2*>(latbase + i * LDIM);
            ulonglong2 p0 = l2[0], p1 = l2[1], p2 = l2[2], p3 = l2[3];
            u64 a0 = 0ull, a1 = 0ull, b0 = 0ull, b1 = 0ull;
            a0 = fma2_(w1a[0], p0.x, a0); a1 = fma2_(w1a[1], p0.y, a1);
            b0 = fma2_(w1b[0], p0.x, b0); b1 = fma2_(w1b[1], p0.y, b1);
            a0 = fma2_(w1a[2], p1.x, a0); a1 = fma2_(w1a[3], p1.y, a1);
            b0 = fma2_(w1b[2], p1.x, b0); b1 = fma2_(w1b[3], p1.y, b1);
            a0 = fma2_(w1a[4], p2.x, a0); a1 = fma2_(w1a[5], p2.y, a1);
            b0 = fma2_(w1b[4], p2.x, b0); b1 = fma2_(w1b[5], p2.y, b1);
            a0 = fma2_(w1a[6], p3.x, a0); a1 = fma2_(w1a[7], p3.y, a1);
            b0 = fma2_(w1b[6], p3.x, b0); b1 = fma2_(w1b[7], p3.y, b1);
            float r0,r1,r2,r3; upk2(r0,r1,a0); upk2(r2,r3,a1);
            float s0 = m0 + ((r0+r1)+(r2+r3));
            upk2(r0,r1,b0); upk2(r2,r3,b1);
            float s1 = m1 + ((r0+r1)+(r2+r3));
            s0 = s0 > 0.f ? s0 : 0.01f * s0;
            s1 = s1 > 0.f ? s1 : 0.01f * s1;
            float al = alb[i];
            sa += al;
            u0 = fmaf(al, s0, u0);
            u1 = fmaf(al, s1, u1);
        }
        sU[w * 68 + lane] = u0; sU[w * 68 + 32 + lane] = u1;
        __syncwarp();
        if (lane < 16) {
            float acc = __ldg(g_q + (size_t)bj * NACTD + lane) + sa * sB2[lane];
            const float* w2r = sW2 + lane * 68;
            const float* uv = sU + w * 68;
            float c0 = 0.f, c1 = 0.f;
#pragma unroll
            for (int o = 0; o < 64; o += 2) {
                c0 = fmaf(w2r[o],   uv[o],   c0);
                c1 = fmaf(w2r[o+1], uv[o+1], c1);
            }
            ret_q[(size_t)bj * NACTD + lane] = acc + c0 + c1;
        }
        __syncwarp();
    }
}

// ---------------- host launcher ----------------
extern "C" void kernel_launch(void* const* d_in, const int* in_sizes, int n_in,
                              void* d_out, int out_size)
{
    (void)in_sizes; (void)n_in; (void)out_size;
    const float* inputs  = (const float*)d_in[0];
    const float* hidden  = (const float*)d_in[1];
    const float* eps     = (const float*)d_in[2];
    const float* fc1_w   = (const float*)d_in[3];
    const float* fc1_b   = (const float*)d_in[4];
    const float* gru_wih = (const float*)d_in[5];
    const float* gru_whh = (const float*)d_in[6];
    const float* gru_bih = (const float*)d_in[7];
    const float* gru_bhh = (const float*)d_in[8];
    const float* fc2_w   = (const float*)d_in[9];
    const float* fc2_b   = (const float*)d_in[10];
    const float* emb_w1  = (const float*)d_in[11];
    const float* emb_b1  = (const float*)d_in[12];
    const float* bn_g    = (const float*)d_in[13];
    const float* bn_b    = (const float*)d_in[14];
    const float* emb_w2  = (const float*)d_in[15];
    const float* emb_b2  = (const float*)d_in[16];
    const float* msg_w1  = (const float*)d_in[17];
    const float* msg_b1  = (const float*)d_in[18];
    const float* msg_w2  = (const float*)d_in[19];
    const float* msg_b2  = (const float*)d_in[20];
    const float* wq_w    = (const float*)d_in[21];
    const float* wq_b    = (const float*)d_in[22];
    const float* wk_w    = (const float*)d_in[23];
    const float* wk_b    = (const float*)d_in[24];

    float* out   = (float*)d_out;
    float* ret_q = out;                          // [32768,16]
    float* h_out = out + (size_t)NROWS * NACTD;  // [32768,64]

    cudaFuncSetAttribute(k1t_trunk,  cudaFuncAttributeMaxDynamicSharedMemorySize, K1_SMEM);
    cudaFuncSetAttribute(k3m_latent, cudaFuncAttributeMaxDynamicSharedMemorySize, K3M_SMEM);
    cudaFuncSetAttribute(k4_msg,     cudaFuncAttributeMaxDynamicSharedMemorySize, K4_SMEM);

    k1t_trunk<<<NROWS / 128, 128, K1_SMEM>>>(
        inputs, hidden, fc1_w, fc1_b, gru_wih, gru_whh, gru_bih, gru_bhh,
        fc2_w, fc2_b, emb_w1, emb_b1, wq_w, wq_b, msg_w1, msg_b1, h_out);

    k2a_bn<<<128, 256>>>();
    k2b_bn<<<1, 256>>>(bn_g, bn_b);

    k3m_latent<<<dim3(NROWS / 128, 2), 128, K3M_SMEM>>>(eps, emb_w2, emb_b2, wk_w, wk_b);

    k4_msg<<<BSZ, 512, K4_SMEM>>>(msg_w1, msg_w2, msg_b2, ret_q);
}

// round 13
// speedup vs baseline: 1.0028x; 1.0028x over previous
#include <cuda_runtime.h>
#include <cuda_bf16.h>
#include <cstdint>

#define NROWS 32768
#define BSZ   1024
#define AGN   32
#define IND   96
#define HDIM  64
#define NNHD  64
#define ATTD  32
#define NACTD 16
#define LDIM  16
#define DLAT  512

typedef unsigned long long u64;

// ---------------- scratch (device globals) ----------------
__device__ float g_z1[NROWS * NNHD];
__device__ float g_q[NROWS * NACTD];
__device__ float g_query[NROWS * ATTD];
__device__ float g_m1h[NROWS * NNHD];
__device__ float g_lat[BSZ * AGN * AGN * LDIM];   // [b][j][i][l]
__device__ float g_alpha[BSZ * AGN * AGN];        // RAW scores [b][j][i]
__device__ float g_bn_a[NNHD];
__device__ float g_bn_c[NNHD];
__device__ float g_p1[128 * NNHD];
__device__ float g_p2[128 * NNHD];

// ---------------- packed f32x2 helpers (k4) ----------------
__device__ __forceinline__ u64 pk2(float lo, float hi) {
    u64 r; asm("mov.b64 %0, {%1, %2};" : "=l"(r) : "f"(lo), "f"(hi)); return r;
}
__device__ __forceinline__ void upk2(float& lo, float& hi, u64 v) {
    asm("mov.b64 {%0, %1}, %2;" : "=f"(lo), "=f"(hi) : "l"(v));
}
__device__ __forceinline__ u64 fma2_(u64 a, u64 b, u64 c) {
    u64 d; asm("fma.rn.f32x2 %0, %1, %2, %3;" : "=l"(d) : "l"(a), "l"(b), "l"(c)); return d;
}
__device__ __forceinline__ void cload(float* dst, const float* __restrict__ src,
                                      int n4, int tid, int nthr) {
    float4* d = reinterpret_cast<float4*>(dst);
    const float4* s = reinterpret_cast<const float4*>(src);
    for (int i = tid; i < n4; i += nthr) d[i] = __ldg(s + i);
}
__device__ __forceinline__ float sigmoidf_(float x) {
    return __fdividef(1.f, 1.f + __expf(-x));
}

// ---------------- warp MMA plumbing ----------------
__device__ __forceinline__ uint32_t smem_u32(const void* p) {
    uint32_t a;
    asm("{ .reg .u64 t; cvta.to.shared.u64 t, %1; cvt.u32.u64 %0, t; }" : "=r"(a) : "l"(p));
    return a;
}
#define SWZ128(o) ((o) ^ (((o) >> 3) & 0x70))
__device__ __forceinline__ void ldsm_x4(uint32_t& r0, uint32_t& r1, uint32_t& r2, uint32_t& r3,
                                        uint32_t addr) {
    asm volatile("ldmatrix.sync.aligned.m8n8.x4.shared.b16 {%0,%1,%2,%3}, [%4];"
                 : "=r"(r0), "=r"(r1), "=r"(r2), "=r"(r3) : "r"(addr));
}
__device__ __forceinline__ void ldsm_x2(uint32_t& r0, uint32_t& r1, uint32_t addr) {
    asm volatile("ldmatrix.sync.aligned.m8n8.x2.shared.b16 {%0,%1}, [%2];"
                 : "=r"(r0), "=r"(r1) : "r"(addr));
}
__device__ __forceinline__ void mma16816(float* d, const uint32_t* a, uint32_t b0, uint32_t b1) {
    asm volatile(
        "mma.sync.aligned.m16n8k16.row.col.f32.bf16.bf16.f32 "
        "{%0,%1,%2,%3}, {%4,%5,%6,%7}, {%8,%9}, {%0,%1,%2,%3};"
        : "+f"(d[0]), "+f"(d[1]), "+f"(d[2]), "+f"(d[3])
        : "r"(a[0]), "r"(a[1]), "r"(a[2]), "r"(a[3]), "r"(b0), "r"(b1));
}
__device__ __forceinline__ void bf_split2(float a, float b, uint32_t& hi, uint32_t& lo) {
    __nv_bfloat16 ha = __float2bfloat16(a), hb = __float2bfloat16(b);
    float ra = a - __bfloat162float(ha);
    float rb = b - __bfloat162float(hb);
    __nv_bfloat162 H = __halves2bfloat162(ha, hb);
    __nv_bfloat162 L = __floats2bfloat162_rn(ra, rb);
    hi = *reinterpret_cast<uint32_t*>(&H);
    lo = *reinterpret_cast<uint32_t*>(&L);
}

template<int NKT, int NTS>
__device__ __forceinline__ void mma_pass(float (&acc)[2][8][4],
    uint32_t aH, uint32_t aL, uint32_t bH, uint32_t bL, int w, int lane)
{
#pragma unroll
    for (int kt = 0; kt < NKT; kt++) {
        uint32_t ah[2][4], al[2][4];
#pragma unroll
        for (int mt = 0; mt < 2; mt++) {
            uint32_t aoff = SWZ128((uint32_t)(
                (w * 32 + mt * 16 + (lane & 15)) * 128 + kt * 32 + (lane >> 4) * 16));
            ldsm_x4(ah[mt][0], ah[mt][1], ah[mt][2], ah[mt][3], aH + aoff);
            ldsm_x4(al[mt][0], al[mt][1], al[mt][2], al[mt][3], aL + aoff);
        }
#pragma unroll
        for (int nt = 0; nt < NTS; nt++) {
            uint32_t boff = SWZ128((uint32_t)(
                (nt * 8 + (lane & 7)) * 128 + kt * 32 + ((lane >> 3) & 1) * 16));
            uint32_t bh0, bh1, bl0, bl1;
            ldsm_x2(bh0, bh1, bH + boff);
            ldsm_x2(bl0, bl1, bL + boff);
#pragma unroll
            for (int mt = 0; mt < 2; mt++) {
                mma16816(acc[mt][nt], ah[mt], bh0, bh1);
                mma16816(acc[mt][nt], ah[mt], bl0, bl1);
                mma16816(acc[mt][nt], al[mt], bh0, bh1);
            }
        }
    }
}

// build [64 n x 64 k] bf16 hi/lo SW128 B tile from row-major gmem
__device__ __forceinline__ void build_b64(char* hi, char* lo,
    const float* __restrict__ src, int stride, int tid)
{
#pragma unroll
    for (int k = 0; k < 8; k++) {
        int idx4 = tid + k * 128;
        int n = idx4 >> 4, c4 = idx4 & 15;
        float4 v = __ldg(reinterpret_cast<const float4*>(src + (size_t)n * stride + c4 * 4));
        uint32_t h0, l0, h1, l1;
        bf_split2(v.x, v.y, h0, l0);
        bf_split2(v.z, v.w, h1, l1);
        uint32_t off = SWZ128((uint32_t)(n * 128 + c4 * 8));
        *reinterpret_cast<uint2*>(hi + off) = make_uint2(h0, h1);
        *reinterpret_cast<uint2*>(lo + off) = make_uint2(l0, l1);
    }
}

__device__ __forceinline__ void init_acc(float (&acc)[2][8][4], const float* sBias, int e0)
{
#pragma unroll
    for (int mt = 0; mt < 2; mt++)
#pragma unroll
        for (int nt = 0; nt < 8; nt++) {
            float b0 = sBias[nt * 8 + e0], b1 = sBias[nt * 8 + e0 + 1];
            acc[mt][nt][0] = b0; acc[mt][nt][1] = b1;
            acc[mt][nt][2] = b0; acc[mt][nt][3] = b1;
        }
}

#define LGSCALE 0.721347520444482f
#define SQVF    0.044721359549996f

// ---------------- K1T: trunk on tensor cores ----------------
#define K1_XA_HI 0
#define K1_XA_LO 16384
#define K1_XB_HI 32768
#define K1_XB_LO 49152
#define K1_H_HI  65536
#define K1_H_LO  81920
#define K1_B0_HI 98304
#define K1_B0_LO 106496
#define K1_B1_HI 114688
#define K1_B1_LO 122880
#define K1_SR    131072
#define K1_SZ    164864
#define K1_SBIAS 198656
#define K1_SMEM  199168

__global__ void __launch_bounds__(128) k1t_trunk(
    const float* __restrict__ inp, const float* __restrict__ h0in,
    const float* __restrict__ fc1_w, const float* __restrict__ fc1_b,
    const float* __restrict__ wih, const float* __restrict__ whh,
    const float* __restrict__ bih, const float* __restrict__ bhh,
    const float* __restrict__ fc2_w, const float* __restrict__ fc2_b,
    const float* __restrict__ emb_w1, const float* __restrict__ emb_b1,
    const float* __restrict__ wq_w, const float* __restrict__ wq_b,
    const float* __restrict__ msg_w1, const float* __restrict__ msg_b1,
    float* __restrict__ h_out)
{
    extern __shared__ char sm[];
    const uint32_t sbase = smem_u32(sm);
    float* smf = reinterpret_cast<float*>(sm);
    float* sBias = smf + K1_SBIAS / 4;
    const int tid = threadIdx.x;
    const int w = tid >> 5;
    const int lane = tid & 31;
    const int e0 = 2 * (lane & 3);
    const int row0 = blockIdx.x * 128;
    const float qs = 0.17677669529663687f;

    // ---- A build ----
    {
        const float4* ip = reinterpret_cast<const float4*>(inp + (size_t)(row0 + tid) * IND);
#pragma unroll
        for (int k = 0; k < 24; k++) {
            float4 v = __ldg(ip + k);
            uint32_t hA, lA, hB, lB;
            bf_split2(v.x, v.y, hA, lA);
            bf_split2(v.z, v.w, hB, lB);
            if (k < 16) {
                uint32_t off = SWZ128((uint32_t)(tid * 128 + k * 8));
                *reinterpret_cast<uint2*>(sm + K1_XA_HI + off) = make_uint2(hA, hB);
                *reinterpret_cast<uint2*>(sm + K1_XA_LO + off) = make_uint2(lA, lB);
            } else {
                uint32_t off = SWZ128((uint32_t)(tid * 128 + (k - 16) * 8));
                *reinterpret_cast<uint2*>(sm + K1_XB_HI + off) = make_uint2(hA, hB);
                *reinterpret_cast<uint2*>(sm + K1_XB_LO + off) = make_uint2(lA, lB);
            }
        }
        const float4* hp = reinterpret_cast<const float4*>(h0in + (size_t)(row0 + tid) * HDIM);
#pragma unroll
        for (int k = 0; k < 16; k++) {
            float4 v = __ldg(hp + k);
            uint32_t hA, lA, hB, lB;
            bf_split2(v.x, v.y, hA, lA);
            bf_split2(v.z, v.w, hB, lB);
            uint32_t off = SWZ128((uint32_t)(tid * 128 + k * 8));
            *reinterpret_cast<uint2*>(sm + K1_H_HI + off) = make_uint2(hA, hB);
            *reinterpret_cast<uint2*>(sm + K1_H_LO + off) = make_uint2(lA, lB);
        }
    }
    build_b64(sm + K1_B0_HI, sm + K1_B0_LO, fc1_w, IND, tid);
#pragma unroll
    for (int k = 0; k < 4; k++) {
        int idx = tid + k * 128;
        int n = idx >> 3, c4 = idx & 7;
        float4 v = __ldg(reinterpret_cast<const float4*>(fc1_w + (size_t)n * IND + 64 + c4 * 4));
        uint32_t h0_, l0_, h1_, l1_;
        bf_split2(v.x, v.y, h0_, l0_);
        bf_split2(v.z, v.w, h1_, l1_);
        uint32_t off = SWZ128((uint32_t)(n * 128 + c4 * 8));
        *reinterpret_cast<uint2*>(sm + K1_B1_HI + off) = make_uint2(h0_, h1_);
        *reinterpret_cast<uint2*>(sm + K1_B1_LO + off) = make_uint2(l0_, l1_);
    }
    if (tid < 64) sBias[tid] = __ldg(fc1_b + tid);
    __syncthreads();

    float acc[2][8][4];

    // ---- fc1 GEMM + relu -> x tile ----
    init_acc(acc, sBias, e0);
    mma_pass<4, 8>(acc, sbase + K1_XA_HI, sbase + K1_XA_LO, sbase + K1_B0_HI, sbase + K1_B0_LO, w, lane);
    mma_pass<2, 8>(acc, sbase + K1_XB_HI, sbase + K1_XB_LO, sbase + K1_B1_HI, sbase + K1_B1_LO, w, lane);
#pragma unroll
    for (int mt = 0; mt < 2; mt++)
#pragma unroll
        for (int h01 = 0; h01 < 2; h01++) {
            int row = w * 32 + mt * 16 + (lane >> 2) + 8 * h01;
#pragma unroll
            for (int nt = 0; nt < 8; nt++) {
                int c = nt * 8 + e0;
                float v0 = fmaxf(acc[mt][nt][h01 * 2 + 0], 0.f);
                float v1 = fmaxf(acc[mt][nt][h01 * 2 + 1], 0.f);
                uint32_t hh, ll;
                bf_split2(v0, v1, hh, ll);
                uint32_t off = SWZ128((uint32_t)(row * 128 + c * 2));
                *reinterpret_cast<uint32_t*>(sm + K1_XA_HI + off) = hh;
                *reinterpret_cast<uint32_t*>(sm + K1_XA_LO + off) = ll;
            }
        }
    __syncthreads();

    // ---- GRU r gate ----
    build_b64(sm + K1_B0_HI, sm + K1_B0_LO, wih, HDIM, tid);
    build_b64(sm + K1_B1_HI, sm + K1_B1_LO, whh, HDIM, tid);
    if (tid < 64) sBias[tid] = __ldg(bih + tid) + __ldg(bhh + tid);
    __syncthreads();
    init_acc(acc, sBias, e0);
    mma_pass<4, 8>(acc, sbase + K1_XA_HI, sbase + K1_XA_LO, sbase + K1_B0_HI, sbase + K1_B0_LO, w, lane);
    mma_pass<4, 8>(acc, sbase + K1_H_HI,  sbase + K1_H_LO,  sbase + K1_B1_HI, sbase + K1_B1_LO, w, lane);
#pragma unroll
    for (int mt = 0; mt < 2; mt++)
#pragma unroll
        for (int h01 = 0; h01 < 2; h01++) {
            int row = w * 32 + mt * 16 + (lane >> 2) + 8 * h01;
#pragma unroll
            for (int nt = 0; nt < 8; nt++) {
                int c = nt * 8 + e0;
                *reinterpret_cast<float2*>(smf + K1_SR / 4 + row * 66 + c) =
                    make_float2(sigmoidf_(acc[mt][nt][h01 * 2 + 0]),
                                sigmoidf_(acc[mt][nt][h01 * 2 + 1]));
            }
        }
    __syncthreads();

    // ---- GRU z gate ----
    build_b64(sm + K1_B0_HI, sm + K1_B0_LO, wih + 64 * HDIM, HDIM, tid);
    build_b64(sm + K1_B1_HI, sm + K1_B1_LO, whh + 64 * HDIM, HDIM, tid);
    if (tid < 64) sBias[tid] = __ldg(bih + 64 + tid) + __ldg(bhh + 64 + tid);
    __syncthreads();
    init_acc(acc, sBias, e0);
    mma_pass<4, 8>(acc, sbase + K1_XA_HI, sbase + K1_XA_LO, sbase + K1_B0_HI, sbase + K1_B0_LO, w, lane);
    mma_pass<4, 8>(acc, sbase + K1_H_HI,  sbase + K1_H_LO,  sbase + K1_B1_HI, sbase + K1_B1_LO, w, lane);
#pragma unroll
    for (int mt = 0; mt < 2; mt++)
#pragma unroll
        for (int h01 = 0; h01 < 2; h01++) {
            int row = w * 32 + mt * 16 + (lane >> 2) + 8 * h01;
#pragma unroll
            for (int nt = 0; nt < 8; nt++) {
                int c = nt * 8 + e0;
                *reinterpret_cast<float2*>(smf + K1_SZ / 4 + row * 66 + c) =
                    make_float2(sigmoidf_(acc[mt][nt][h01 * 2 + 0]),
                                sigmoidf_(acc[mt][nt][h01 * 2 + 1]));
            }
        }
    __syncthreads();

    // ---- GRU n gate ----
    build_b64(sm + K1_B0_HI, sm + K1_B0_LO, wih + 128 * HDIM, HDIM, tid);
    build_b64(sm + K1_B1_HI, sm + K1_B1_LO, whh + 128 * HDIM, HDIM, tid);
    if (tid < 64) sBias[tid] = __ldg(bih + 128 + tid);
    else sBias[tid] = __ldg(bhh + 128 + (tid - 64));
    __syncthreads();
    float acc2[2][8][4];
    init_acc(acc, sBias, e0);
    init_acc(acc2, sBias + 64, e0);
    mma_pass<4, 8>(acc,  sbase + K1_XA_HI, sbase + K1_XA_LO, sbase + K1_B0_HI, sbase + K1_B0_LO, w, lane);
    mma_pass<4, 8>(acc2, sbase + K1_H_HI,  sbase + K1_H_LO,  sbase + K1_B1_HI, sbase + K1_B1_LO, w, lane);

    // ---- blend ----
#pragma unroll
    for (int mt = 0; mt < 2; mt++)
#pragma unroll
        for (int h01 = 0; h01 < 2; h01++) {
            int row = w * 32 + mt * 16 + (lane >> 2) + 8 * h01;
            int grow = row0 + row;
#pragma unroll
            for (int nt = 0; nt < 8; nt++) {
                int c = nt * 8 + e0;
                float2 rv = *reinterpret_cast<const float2*>(smf + K1_SR / 4 + row * 66 + c);
                float2 zv = *reinterpret_cast<const float2*>(smf + K1_SZ / 4 + row * 66 + c);
                float n0 = tanhf(acc[mt][nt][h01 * 2 + 0] + rv.x * acc2[mt][nt][h01 * 2 + 0]);
                float n1 = tanhf(acc[mt][nt][h01 * 2 + 1] + rv.y * acc2[mt][nt][h01 * 2 + 1]);
                float2 h0v = __ldg(reinterpret_cast<const float2*>(h0in + (size_t)grow * HDIM + c));
                float hn0 = (1.f - zv.x) * n0 + zv.x * h0v.x;
                float hn1 = (1.f - zv.y) * n1 + zv.y * h0v.y;
                *reinterpret_cast<float2*>(h_out + (size_t)grow * HDIM + c) = make_float2(hn0, hn1);
                uint32_t hh, ll;
                bf_split2(hn0, hn1, hh, ll);
                uint32_t off = SWZ128((uint32_t)(row * 128 + c * 2));
                *reinterpret_cast<uint32_t*>(sm + K1_H_HI + off) = hh;
                *reinterpret_cast<uint32_t*>(sm + K1_H_LO + off) = ll;
            }
        }
    __syncthreads();

    // ---- heads ----
#pragma unroll
    for (int p = 0; p < 3; p++) {
        const int rows = (p == 2) ? 48 : 64;
#pragma unroll
        for (int k = 0; k < 8; k++) {
            int idx4 = tid + k * 128;
            int n = idx4 >> 4, c4 = idx4 & 15;
            if (n < rows) {
                int g = p * 64 + n;
                const float* src; float sc = 1.f;
                if (g < 16)       src = fc2_w + (size_t)g * HDIM;
                else if (g < 80)  src = emb_w1 + (size_t)(g - 16) * HDIM;
                else if (g < 112) { src = wq_w + (size_t)(g - 80) * HDIM; sc = qs; }
                else              src = msg_w1 + (size_t)(g - 112) * 80;
                float4 v = __ldg(reinterpret_cast<const float4*>(src + c4 * 4));
                uint32_t h0_, l0_, h1_, l1_;
                bf_split2(v.x * sc, v.y * sc, h0_, l0_);
                bf_split2(v.z * sc, v.w * sc, h1_, l1_);
                uint32_t off = SWZ128((uint32_t)(n * 128 + c4 * 8));
                *reinterpret_cast<uint2*>(sm + K1_B0_HI + off) = make_uint2(h0_, h1_);
                *reinterpret_cast<uint2*>(sm + K1_B0_LO + off) = make_uint2(l0_, l1_);
            }
        }
        if (tid < rows) {
            int g = p * 64 + tid; float bv;
            if (g < 16)       bv = __ldg(fc2_b + g);
            else if (g < 80)  bv = __ldg(emb_b1 + g - 16);
            else if (g < 112) bv = __ldg(wq_b + g - 80) * qs;
            else              bv = __ldg(msg_b1 + g - 112);
            sBias[tid] = bv;
        }
        __syncthreads();
        init_acc(acc, sBias, e0);
        if (p == 2)
            mma_pass<4, 6>(acc, sbase + K1_H_HI, sbase + K1_H_LO, sbase + K1_B0_HI, sbase + K1_B0_LO, w, lane);
        else
            mma_pass<4, 8>(acc, sbase + K1_H_HI, sbase + K1_H_LO, sbase + K1_B0_HI, sbase + K1_B0_LO, w, lane);
        const int nts = (p == 2) ? 6 : 8;
#pragma unroll
        for (int mt = 0; mt < 2; mt++)
#pragma unroll
            for (int h01 = 0; h01 < 2; h01++) {
                int row = w * 32 + mt * 16 + (lane >> 2) + 8 * h01;
                int grow = row0 + row;
                for (int nt = 0; nt < nts; nt++) {
                    int cg = p * 64 + nt * 8 + e0;
                    float v0 = acc[mt][nt][h01 * 2 + 0];
                    float v1 = acc[mt][nt][h01 * 2 + 1];
                    float* dst;
                    if (cg < 16)       dst = g_q + (size_t)grow * NACTD + cg;
                    else if (cg < 80)  dst = g_z1 + (size_t)grow * NNHD + (cg - 16);
                    else if (cg < 112) dst = g_query + (size_t)grow * ATTD + (cg - 80);
                    else               dst = g_m1h + (size_t)grow * NNHD + (cg - 112);
                    *reinterpret_cast<float2*>(dst) = make_float2(v0, v1);
                }
            }
        __syncthreads();
    }
}

// ---------------- K2a/K2b: BN statistics (R10 versions) ----------------
__global__ void __launch_bounds__(256) k2a_bn()
{
    __shared__ float ss[4][NNHD], sq[4][NNHD];
    const int tid = threadIdx.x;
    const int f = tid & 63;
    const int rg = tid >> 6;
    const int base = blockIdx.x * 256;
    float s = 0.f, q = 0.f;
    for (int r = rg; r < 256; r += 4) {
        float v = g_z1[(size_t)(base + r) * NNHD + f];
        s += v; q += v * v;
    }
    ss[rg][f] = s; sq[rg][f] = q;
    __syncthreads();
    if (tid < NNHD) {
        g_p1[blockIdx.x * NNHD + tid] = ss[0][tid] + ss[1][tid] + ss[2][tid] + ss[3][tid];
        g_p2[blockIdx.x * NNHD + tid] = sq[0][tid] + sq[1][tid] + sq[2][tid] + sq[3][tid];
    }
}
__global__ void __launch_bounds__(256) k2b_bn(const float* __restrict__ bn_g,
                                              const float* __restrict__ bn_b)
{
    __shared__ float ss[256], sq[256];
    const int tid = threadIdx.x;
    const int f = tid & 63;
    const int rg = tid >> 6;
    float s = 0.f, q = 0.f;
#pragma unroll
    for (int i = rg; i < 128; i += 4) {
        s += g_p1[i * NNHD + f];
        q += g_p2[i * NNHD + f];
    }
    ss[tid] = s; sq[tid] = q;
    __syncthreads();
    if (tid < NNHD) {
        float S = ss[f] + ss[64 + f] + ss[128 + f] + ss[192 + f];
        float Q = sq[f] + sq[64 + f] + sq[128 + f] + sq[192 + f];
        float mean = S * (1.f / (float)NROWS);
        float var  = Q * (1.f / (float)NROWS) - mean * mean;
        float a = __ldg(bn_g + f) / sqrtf(var + 1e-5f);
        g_bn_a[f] = a;
        g_bn_c[f] = __ldg(bn_b + f) - a * mean;
    }
}

// ---------------- K3m: latent GEMM, t-split + forced 3 CTA/SM ----------------
#define K3M_SA_HI 0
#define K3M_SA_LO 16384
#define K3M_SB_HI 32768
#define K3M_SB_LO 49152
#define K3M_SQK   65536
#define K3M_SQB   73728
#define K3M_SWK   74240
#define K3M_SBIAS 76288
#define K3M_SMEM  76800

__global__ void __launch_bounds__(128, 3) k3m_latent(
    const float* __restrict__ eps,
    const float* __restrict__ emb_w2, const float* __restrict__ emb_b2,
    const float* __restrict__ wk_w, const float* __restrict__ wk_b)
{
    extern __shared__ char sm[];
    const uint32_t sbase = smem_u32(sm);
    float* smf = reinterpret_cast<float*>(sm);
    const int tid = threadIdx.x;
    const int w = tid >> 5;
    const int lane = tid & 31;
    const int row0 = blockIdx.x * 128;
    const int b = blockIdx.x * 4 + w;
    const int e0 = 2 * (lane & 3);

    {
        const float4* zpg = reinterpret_cast<const float4*>(g_z1 + (size_t)(row0 + tid) * NNHD);
#pragma unroll
        for (int k = 0; k < 16; k++) {
            float4 v = __ldg(zpg + k);
            float t0 = g_bn_a[4*k+0] * v.x + g_bn_c[4*k+0]; t0 = t0 > 0.f ? t0 : 0.01f * t0;
            float t1 = g_bn_a[4*k+1] * v.y + g_bn_c[4*k+1]; t1 = t1 > 0.f ? t1 : 0.01f * t1;
            float t2 = g_bn_a[4*k+2] * v.z + g_bn_c[4*k+2]; t2 = t2 > 0.f ? t2 : 0.01f * t2;
            float t3 = g_bn_a[4*k+3] * v.w + g_bn_c[4*k+3]; t3 = t3 > 0.f ? t3 : 0.01f * t3;
            uint32_t h0, l0, h1, l1;
            bf_split2(t0, t1, h0, l0);
            bf_split2(t2, t3, h1, l1);
            uint32_t off = SWZ128((uint32_t)(tid * 128 + k * 8));
            *reinterpret_cast<uint2*>(sm + K3M_SA_HI + off) = make_uint2(h0, h1);
            *reinterpret_cast<uint2*>(sm + K3M_SA_LO + off) = make_uint2(l0, l1);
        }
    }
    cload(smf + K3M_SWK / 4, wk_w, 128, tid, 128);
    __syncthreads();

    {
        const float* swk = smf + K3M_SWK / 4;
        float qk[16];
#pragma unroll
        for (int l = 0; l < 16; l++) qk[l] = 0.f;
        float qb = 0.f;
        const float4* qp = reinterpret_cast<const float4*>(g_query + (size_t)(row0 + tid) * ATTD);
#pragma unroll
        for (int k = 0; k < 8; k++) {
            float4 v = __ldg(qp + k);
            float qa[4] = {v.x, v.y, v.z, v.w};
#pragma unroll
            for (int u = 0; u < 4; u++) {
                int a = 4*k + u;
#pragma unroll
                for (int l = 0; l < 16; l++) qk[l] = fmaf(qa[u], swk[a*16 + l], qk[l]);
                qb = fmaf(qa[u], __ldg(wk_b + a), qb);
            }
        }
#pragma unroll
        for (int l = 0; l < 16; l++) smf[K3M_SQK / 4 + tid * 16 + l] = qk[l];
        smf[K3M_SQB / 4 + tid] = qb;
    }
    __syncthreads();

    float qkr[4][4], qbr[4];
#pragma unroll
    for (int rr = 0; rr < 4; rr++) {
        int rloc = w * 32 + ((rr >> 1) ? 16 : 0) + (lane >> 2) + ((rr & 1) ? 8 : 0);
        const float* q = smf + K3M_SQK / 4 + rloc * 16;
        qkr[rr][0] = q[e0]; qkr[rr][1] = q[e0 + 1];
        qkr[rr][2] = q[e0 + 8]; qkr[rr][3] = q[e0 + 9];
        qbr[rr] = smf[K3M_SQB / 4 + rloc];
    }

    for (int tt = 0; tt < 4; tt++) {
        const int t = blockIdx.y * 4 + tt;
        if (tt > 0) __syncthreads();
#pragma unroll
        for (int k = 0; k < 16; k++) {
            int idx4 = tid + k * 128;
            int n = idx4 >> 4, c4 = idx4 & 15;
            int h = n >> 6, q = (n >> 5) & 1;
            int dl = 32 * h + (n & 31);
            int wrow = (q ? 512 : 0) + 64 * t + dl;
            float sc = q ? LGSCALE : 1.f;
            float4 v = __ldg(reinterpret_cast<const float4*>(emb_w2 + wrow * 64 + c4 * 4));
            uint32_t h0, l0, h1, l1;
            bf_split2(v.x * sc, v.y * sc, h0, l0);
            bf_split2(v.z * sc, v.w * sc, h1, l1);
            uint32_t off = SWZ128((uint32_t)(n * 128 + c4 * 8));
            *reinterpret_cast<uint2*>(sm + K3M_SB_HI + off) = make_uint2(h0, h1);
            *reinterpret_cast<uint2*>(sm + K3M_SB_LO + off) = make_uint2(l0, l1);
        }
        {
            int n = tid;
            int h = n >> 6, q = (n >> 5) & 1;
            int dl = 32 * h + (n & 31);
            float bv = __ldg(emb_b2 + (q ? 512 : 0) + 64 * t + dl);
            smf[K3M_SBIAS / 4 + n] = q ? bv * LGSCALE : bv;
        }
        __syncthreads();

        for (int hh = 0; hh < 2; hh++) {
            const int nbase = hh * 64;
            float acc[2][8][4];
#pragma unroll
            for (int mt = 0; mt < 2; mt++)
#pragma unroll
                for (int nt = 0; nt < 8; nt++) {
                    float b0 = smf[K3M_SBIAS / 4 + nbase + nt * 8 + e0];
                    float b1 = smf[K3M_SBIAS / 4 + nbase + nt * 8 + e0 + 1];
                    acc[mt][nt][0] = b0; acc[mt][nt][1] = b1;
                    acc[mt][nt][2] = b0; acc[mt][nt][3] = b1;
                }
#pragma unroll
            for (int kt = 0; kt < 4; kt++) {
                uint32_t ah[2][4], al[2][4];
#pragma unroll
                for (int mt = 0; mt < 2; mt++) {
                    uint32_t aoff = SWZ128((uint32_t)(
                        (w * 32 + mt * 16 + (lane & 15)) * 128 + kt * 32 + (lane >> 4) * 16));
                    ldsm_x4(ah[mt][0], ah[mt][1], ah[mt][2], ah[mt][3], sbase + K3M_SA_HI + aoff);
                    ldsm_x4(al[mt][0], al[mt][1], al[mt][2], al[mt][3], sbase + K3M_SA_LO + aoff);
                }
#pragma unroll
                for (int nt = 0; nt < 8; nt++) {
                    uint32_t boff = SWZ128((uint32_t)(
                        (nbase + nt * 8 + (lane & 7)) * 128 + kt * 32 + ((lane >> 3) & 1) * 16));
                    uint32_t bh0, bh1, bl0, bl1;
                    ldsm_x2(bh0, bh1, sbase + K3M_SB_HI + boff);
                    ldsm_x2(bl0, bl1, sbase + K3M_SB_LO + boff);
#pragma unroll
                    for (int mt = 0; mt < 2; mt++) {
                        mma16816(acc[mt][nt], ah[mt], bh0, bh1);
                        mma16816(acc[mt][nt], ah[mt], bl0, bl1);
                        mma16816(acc[mt][nt], al[mt], bh0, bh1);
                    }
                }
            }
#pragma unroll
            for (int mt = 0; mt < 2; mt++) {
#pragma unroll
                for (int h01 = 0; h01 < 2; h01++) {
                    const int rloc = w * 32 + mt * 16 + (lane >> 2) + 8 * h01;
                    const int rr = mt * 2 + h01;
                    const int i = rloc & 31;
                    float ap0 = 0.f, ap1 = 0.f;
#pragma unroll
                    for (int nt = 0; nt < 4; nt++) {
                        const int c = nt * 8 + e0;
                        float mu0 = acc[mt][nt][h01*2+0];
                        float mu1 = acc[mt][nt][h01*2+1];
                        float lg0 = acc[mt][nt+4][h01*2+0];
                        float lg1 = acc[mt][nt+4][h01*2+1];
                        float s0 = fmaxf(exp2f(lg0), SQVF);
                        float s1 = fmaxf(exp2f(lg1), SQVF);
                        const int dglob = t * 64 + 32 * hh + c;
                        float2 ev = __ldg(reinterpret_cast<const float2*>(
                            eps + (size_t)(row0 + rloc) * DLAT + dglob));
                        float l0 = fmaf(s0, ev.x, mu0);
                        float l1 = fmaf(s1, ev.y, mu1);
                        const int j = 4 * t + 2 * hh + (c >> 4);
                        const int pos = c & 15;
                        *reinterpret_cast<float2*>(
                            g_lat + (((size_t)(b * AGN + j)) * AGN + i) * LDIM + pos)
                            = make_float2(l0, l1);
                        float pa = qkr[rr][(nt & 1) * 2 + 0] * l0
                                 + qkr[rr][(nt & 1) * 2 + 1] * l1;
                        if (nt < 2) ap0 += pa; else ap1 += pa;
                    }
                    ap0 += __shfl_xor_sync(0xffffffffu, ap0, 1);
                    ap0 += __shfl_xor_sync(0xffffffffu, ap0, 2);
                    ap1 += __shfl_xor_sync(0xffffffffu, ap1, 1);
                    ap1 += __shfl_xor_sync(0xffffffffu, ap1, 2);
                    if ((lane & 3) == 0) {
                        int j0 = 4 * t + 2 * hh;
                        g_alpha[((size_t)(b * AGN + j0)) * AGN + i]     = ap0 + qbr[rr];
                        g_alpha[((size_t)(b * AGN + j0 + 1)) * AGN + i] = ap1 + qbr[rr];
                    }
                }
            }
        }
    }
}

// ---------------- K4: softmax + message MLP + aggregate (R10 256-thread version) ----------------
#define K4_SMEM ((16384 + 16 * 68 + 16 + 32 * 33 + 8 * 68) * 4)
__global__ void __launch_bounds__(256) k4_msg(
    const float* __restrict__ msg_w1,
    const float* __restrict__ msg_w2, const float* __restrict__ msg_b2,
    float* __restrict__ ret_q)
{
    extern __shared__ float sm4[];
    float* latS = sm4;
    float* sW2  = sm4 + 16384;
    float* sB2  = sW2 + 16 * 68;
    float* sal  = sB2 + 16;
    float* sU   = sal + 32 * 33;
    const int tid = threadIdx.x;
    const int w = tid >> 5;
    const int lane = tid & 31;
    const int b = blockIdx.x;

    {
        const float4* latg = reinterpret_cast<const float4*>(g_lat + (size_t)b * 16384);
        float4* latd = reinterpret_cast<float4*>(latS);
#pragma unroll
        for (int i = 0; i < 16; i++)
            latd[tid + i * 256] = __ldg(latg + tid + i * 256);
    }
    for (int idx = tid; idx < 16 * 64; idx += 256) {
        int rr = idx >> 6, cc = idx & 63;
        sW2[rr * 68 + cc] = __ldg(msg_w2 + idx);
    }
    if (tid < 16) sB2[tid] = __ldg(msg_b2 + tid);
    for (int idx = tid; idx < 1024; idx += 256) {
        int jj = idx >> 5, ii = idx & 31;
        sal[jj * 33 + ii] = g_alpha[(size_t)b * 1024 + idx];
    }

    u64 w1a[8], w1b[8];
    {
        const float4* p0 = reinterpret_cast<const float4*>(msg_w1 + lane * 80 + 64);
        const float4* p1 = reinterpret_cast<const float4*>(msg_w1 + (lane + 32) * 80 + 64);
#pragma unroll
        for (int k = 0; k < 4; k++) {
            float4 v0 = __ldg(p0 + k), v1 = __ldg(p1 + k);
            w1a[2*k] = pk2(v0.x, v0.y); w1a[2*k+1] = pk2(v0.z, v0.w);
            w1b[2*k] = pk2(v1.x, v1.y); w1b[2*k+1] = pk2(v1.z, v1.w);
        }
    }
    __syncthreads();

    if (tid < 32) {
        const int ii = tid;
        float m = -3.4e38f;
#pragma unroll
        for (int j = 0; j < AGN; j++) {
            float v = (j == ii) ? -1e9f : sal[j * 33 + ii];
            m = fmaxf(m, v);
        }
        float s = 0.f;
#pragma unroll
        for (int j = 0; j < AGN; j++) {
            float v = (j == ii) ? -1e9f : sal[j * 33 + ii];
            float e = expf(v - m);
            sal[j * 33 + ii] = e;
            s += e;
        }
        float inv = 1.f / s;
#pragma unroll
        for (int j = 0; j < AGN; j++) sal[j * 33 + ii] *= inv;
    }
    __syncthreads();

#pragma unroll
    for (int jj = 0; jj < 4; jj++) {
        const int j = w + jj * 8;
        const int bj = b * AGN + j;
        const float m0 = __ldg(g_m1h + (size_t)bj * NNHD + lane);
        const float m1 = __ldg(g_m1h + (size_t)bj * NNHD + 32 + lane);
        const float* latbase = latS + j * 512;
        const float* alb = sal + j * 33;
        float u0 = 0.f, u1 = 0.f, sa = 0.f;

        for (int i = 0; i < AGN; i++) {
            const ulonglong2* l2 = reinterpret_cast<const ulonglong2*>(latbase + i * LDIM);
            ulonglong2 p0 = l2[0], p1 = l2[1], p2 = l2[2], p3 = l2[3];
            u64 a0 = 0ull, a1 = 0ull, b0 = 0ull, b1 = 0ull;
            a0 = fma2_(w1a[0], p0.x, a0); a1 = fma2_(w1a[1], p0.y, a1);
            b0 = fma2_(w1b[0], p0.x, b0); b1 = fma2_(w1b[1], p0.y, b1);
            a0 = fma2_(w1a[2], p1.x, a0); a1 = fma2_(w1a[3], p1.y, a1);
            b0 = fma2_(w1b[2], p1.x, b0); b1 = fma2_(w1b[3], p1.y, b1);
            a0 = fma2_(w1a[4], p2.x, a0); a1 = fma2_(w1a[5], p2.y, a1);
            b0 = fma2_(w1b[4], p2.x, b0); b1 = fma2_(w1b[5], p2.y, b1);
            a0 = fma2_(w1a[6], p3.x, a0); a1 = fma2_(w1a[7], p3.y, a1);
            b0 = fma2_(w1b[6], p3.x, b0); b1 = fma2_(w1b[7], p3.y, b1);
            float r0,r1,r2,r3; upk2(r0,r1,a0); upk2(r2,r3,a1);
            float s0 = m0 + ((r0+r1)+(r2+r3));
            upk2(r0,r1,b0); upk2(r2,r3,b1);
            float s1 = m1 + ((r0+r1)+(r2+r3));
            s0 = s0 > 0.f ? s0 : 0.01f * s0;
            s1 = s1 > 0.f ? s1 : 0.01f * s1;
            float al = alb[i];
            sa += al;
            u0 = fmaf(al, s0, u0);
            u1 = fmaf(al, s1, u1);
        }
        sU[w * 68 + lane] = u0; sU[w * 68 + 32 + lane] = u1;
        __syncwarp();
        if (lane < 16) {
            float acc = __ldg(g_q + (size_t)bj * NACTD + lane) + sa * sB2[lane];
            const float* w2r = sW2 + lane * 68;
            const float* uv = sU + w * 68;
            float c0 = 0.f, c1 = 0.f;
#pragma unroll
            for (int o = 0; o < 64; o += 2) {
                c0 = fmaf(w2r[o],   uv[o],   c0);
                c1 = fmaf(w2r[o+1], uv[o+1], c1);
            }
            ret_q[(size_t)bj * NACTD + lane] = acc + c0 + c1;
        }
        __syncwarp();
    }
}

// ---------------- host launcher ----------------
extern "C" void kernel_launch(void* const* d_in, const int* in_sizes, int n_in,
                              void* d_out, int out_size)
{
    (void)in_sizes; (void)n_in; (void)out_size;
    const float* inputs  = (const float*)d_in[0];
    const float* hidden  = (const float*)d_in[1];
    const float* eps     = (const float*)d_in[2];
    const float* fc1_w   = (const float*)d_in[3];
    const float* fc1_b   = (const float*)d_in[4];
    const float* gru_wih = (const float*)d_in[5];
    const float* gru_whh = (const float*)d_in[6];
    const float* gru_bih = (const float*)d_in[7];
    const float* gru_bhh = (const float*)d_in[8];
    const float* fc2_w   = (const float*)d_in[9];
    const float* fc2_b   = (const float*)d_in[10];
    const float* emb_w1  = (const float*)d_in[11];
    const float* emb_b1  = (const float*)d_in[12];
    const float* bn_g    = (const float*)d_in[13];
    const float* bn_b    = (const float*)d_in[14];
    const float* emb_w2  = (const float*)d_in[15];
    const float* emb_b2  = (const float*)d_in[16];
    const float* msg_w1  = (const float*)d_in[17];
    const float* msg_b1  = (const float*)d_in[18];
    const float* msg_w2  = (const float*)d_in[19];
    const float* msg_b2  = (const float*)d_in[20];
    const float* wq_w    = (const float*)d_in[21];
    const float* wq_b    = (const float*)d_in[22];
    const float* wk_w    = (const float*)d_in[23];
    const float* wk_b    = (const float*)d_in[24];

    float* out   = (float*)d_out;
    float* ret_q = out;                          // [32768,16]
    float* h_out = out + (size_t)NROWS * NACTD;  // [32768,64]

    cudaFuncSetAttribute(k1t_trunk,  cudaFuncAttributeMaxDynamicSharedMemorySize, K1_SMEM);
    cudaFuncSetAttribute(k3m_latent, cudaFuncAttributeMaxDynamicSharedMemorySize, K3M_SMEM);
    cudaFuncSetAttribute(k4_msg,     cudaFuncAttributeMaxDynamicSharedMemorySize, K4_SMEM);

    k1t_trunk<<<NROWS / 128, 128, K1_SMEM>>>(
        inputs, hidden, fc1_w, fc1_b, gru_wih, gru_whh, gru_bih, gru_bhh,
        fc2_w, fc2_b, emb_w1, emb_b1, wq_w, wq_b, msg_w1, msg_b1, h_out);

    k2a_bn<<<128, 256>>>();
    k2b_bn<<<1, 256>>>(bn_g, bn_b);

    k3m_latent<<<dim3(NROWS / 128, 2), 128, K3M_SMEM>>>(eps, emb_w2, emb_b2, wk_w, wk_b);

    k4_msg<<<BSZ, 256, K4_SMEM>>>(msg_w1, msg_w2, msg_b2, ret_q);
}

// round 16
// speedup vs baseline: 1.2551x; 1.2515x over previous
#include <cuda_runtime.h>
#include <cuda_bf16.h>
#include <cstdint>

#define NROWS 32768
#define BSZ   1024
#define AGN   32
#define IND   96
#define HDIM  64
#define NNHD  64
#define ATTD  32
#define NACTD 16
#define LDIM  16
#define DLAT  512

typedef unsigned long long u64;

// ---------------- scratch (device globals) ----------------
__device__ float g_z1[NROWS * NNHD];
__device__ float g_q[NROWS * NACTD];
__device__ float g_query[NROWS * ATTD];
__device__ float g_m1h[NROWS * NNHD];
__device__ float g_lat[BSZ * AGN * AGN * LDIM];   // [b][j][i][l]
__device__ float g_alpha[BSZ * AGN * AGN];        // RAW scores [b][j][i]
__device__ float g_bn_a[NNHD];
__device__ float g_bn_c[NNHD];
__device__ float g_p1[128 * NNHD];
__device__ float g_p2[128 * NNHD];

// ---------------- packed f32x2 helpers (k4) ----------------
__device__ __forceinline__ u64 pk2(float lo, float hi) {
    u64 r; asm("mov.b64 %0, {%1, %2};" : "=l"(r) : "f"(lo), "f"(hi)); return r;
}
__device__ __forceinline__ void upk2(float& lo, float& hi, u64 v) {
    asm("mov.b64 {%0, %1}, %2;" : "=f"(lo), "=f"(hi) : "l"(v));
}
__device__ __forceinline__ u64 fma2_(u64 a, u64 b, u64 c) {
    u64 d; asm("fma.rn.f32x2 %0, %1, %2, %3;" : "=l"(d) : "l"(a), "l"(b), "l"(c)); return d;
}
__device__ __forceinline__ void cload(float* dst, const float* __restrict__ src,
                                      int n4, int tid, int nthr) {
    float4* d = reinterpret_cast<float4*>(dst);
    const float4* s = reinterpret_cast<const float4*>(src);
    for (int i = tid; i < n4; i += nthr) d[i] = __ldg(s + i);
}
__device__ __forceinline__ float sigmoidf_(float x) {
    return __fdividef(1.f, 1.f + __expf(-x));
}

// ---------------- warp MMA plumbing ----------------
__device__ __forceinline__ uint32_t smem_u32(const void* p) {
    uint32_t a;
    asm("{ .reg .u64 t; cvta.to.shared.u64 t, %1; cvt.u32.u64 %0, t; }" : "=r"(a) : "l"(p));
    return a;
}
#define SWZ128(o) ((o) ^ (((o) >> 3) & 0x70))
__device__ __forceinline__ void ldsm_x4(uint32_t& r0, uint32_t& r1, uint32_t& r2, uint32_t& r3,
                                        uint32_t addr) {
    asm volatile("ldmatrix.sync.aligned.m8n8.x4.shared.b16 {%0,%1,%2,%3}, [%4];"
                 : "=r"(r0), "=r"(r1), "=r"(r2), "=r"(r3) : "r"(addr));
}
__device__ __forceinline__ void ldsm_x2(uint32_t& r0, uint32_t& r1, uint32_t addr) {
    asm volatile("ldmatrix.sync.aligned.m8n8.x2.shared.b16 {%0,%1}, [%2];"
                 : "=r"(r0), "=r"(r1) : "r"(addr));
}
__device__ __forceinline__ void mma16816(float* d, const uint32_t* a, uint32_t b0, uint32_t b1) {
    asm volatile(
        "mma.sync.aligned.m16n8k16.row.col.f32.bf16.bf16.f32 "
        "{%0,%1,%2,%3}, {%4,%5,%6,%7}, {%8,%9}, {%0,%1,%2,%3};"
        : "+f"(d[0]), "+f"(d[1]), "+f"(d[2]), "+f"(d[3])
        : "r"(a[0]), "r"(a[1]), "r"(a[2]), "r"(a[3]), "r"(b0), "r"(b1));
}
__device__ __forceinline__ void bf_split2(float a, float b, uint32_t& hi, uint32_t& lo) {
    __nv_bfloat16 ha = __float2bfloat16(a), hb = __float2bfloat16(b);
    float ra = a - __bfloat162float(ha);
    float rb = b - __bfloat162float(hb);
    __nv_bfloat162 H = __halves2bfloat162(ha, hb);
    __nv_bfloat162 L = __floats2bfloat162_rn(ra, rb);
    hi = *reinterpret_cast<uint32_t*>(&H);
    lo = *reinterpret_cast<uint32_t*>(&L);
}

// full-warp version (k3m): 8 N-tiles per warp
template<int NKT, int NTS>
__device__ __forceinline__ void mma_pass(float (&acc)[2][8][4],
    uint32_t aH, uint32_t aL, uint32_t bH, uint32_t bL, int w, int lane)
{
#pragma unroll
    for (int kt = 0; kt < NKT; kt++) {
        uint32_t ah[2][4], al[2][4];
#pragma unroll
        for (int mt = 0; mt < 2; mt++) {
            uint32_t aoff = SWZ128((uint32_t)(
                (w * 32 + mt * 16 + (lane & 15)) * 128 + kt * 32 + (lane >> 4) * 16));
            ldsm_x4(ah[mt][0], ah[mt][1], ah[mt][2], ah[mt][3], aH + aoff);
            ldsm_x4(al[mt][0], al[mt][1], al[mt][2], al[mt][3], aL + aoff);
        }
#pragma unroll
        for (int nt = 0; nt < NTS; nt++) {
            uint32_t boff = SWZ128((uint32_t)(
                (nt * 8 + (lane & 7)) * 128 + kt * 32 + ((lane >> 3) & 1) * 16));
            uint32_t bh0, bh1, bl0, bl1;
            ldsm_x2(bh0, bh1, bH + boff);
            ldsm_x2(bl0, bl1, bL + boff);
#pragma unroll
            for (int mt = 0; mt < 2; mt++) {
                mma16816(acc[mt][nt], ah[mt], bh0, bh1);
                mma16816(acc[mt][nt], ah[mt], bl0, bl1);
                mma16816(acc[mt][nt], al[mt], bh0, bh1);
            }
        }
    }
}

// half-N version (k1t, 8-warp CTA): this warp covers B tiles [nt0, nt0+NTS)
template<int NKT, int NTS>
__device__ __forceinline__ void mma_pass2(float (&acc)[2][4][4],
    uint32_t aH, uint32_t aL, uint32_t bH, uint32_t bL, int wm, int lane, int nt0)
{
#pragma unroll
    for (int kt = 0; kt < NKT; kt++) {
        uint32_t ah[2][4], al[2][4];
#pragma unroll
        for (int mt = 0; mt < 2; mt++) {
            uint32_t aoff = SWZ128((uint32_t)(
                (wm * 32 + mt * 16 + (lane & 15)) * 128 + kt * 32 + (lane >> 4) * 16));
            ldsm_x4(ah[mt][0], ah[mt][1], ah[mt][2], ah[mt][3], aH + aoff);
            ldsm_x4(al[mt][0], al[mt][1], al[mt][2], al[mt][3], aL + aoff);
        }
#pragma unroll
        for (int nt = 0; nt < NTS; nt++) {
            uint32_t boff = SWZ128((uint32_t)(
                ((nt0 + nt) * 8 + (lane & 7)) * 128 + kt * 32 + ((lane >> 3) & 1) * 16));
            uint32_t bh0, bh1, bl0, bl1;
            ldsm_x2(bh0, bh1, bH + boff);
            ldsm_x2(bl0, bl1, bL + boff);
#pragma unroll
            for (int mt = 0; mt < 2; mt++) {
                mma16816(acc[mt][nt], ah[mt], bh0, bh1);
                mma16816(acc[mt][nt], ah[mt], bl0, bl1);
                mma16816(acc[mt][nt], al[mt], bh0, bh1);
            }
        }
    }
}

// build [64 n x 64 k] tile, 128-thread version (k3m)
__device__ __forceinline__ void build_b64(char* hi, char* lo,
    const float* __restrict__ src, int stride, int tid)
{
#pragma unroll
    for (int k = 0; k < 8; k++) {
        int idx4 = tid + k * 128;
        int n = idx4 >> 4, c4 = idx4 & 15;
        float4 v = __ldg(reinterpret_cast<const float4*>(src + (size_t)n * stride + c4 * 4));
        uint32_t h0, l0, h1, l1;
        bf_split2(v.x, v.y, h0, l0);
        bf_split2(v.z, v.w, h1, l1);
        uint32_t off = SWZ128((uint32_t)(n * 128 + c4 * 8));
        *reinterpret_cast<uint2*>(hi + off) = make_uint2(h0, h1);
        *reinterpret_cast<uint2*>(lo + off) = make_uint2(l0, l1);
    }
}
// 256-thread version (k1t)
__device__ __forceinline__ void build_b64_256(char* hi, char* lo,
    const float* __restrict__ src, int stride, int tid)
{
#pragma unroll
    for (int k = 0; k < 4; k++) {
        int idx4 = tid + k * 256;
        int n = idx4 >> 4, c4 = idx4 & 15;
        float4 v = __ldg(reinterpret_cast<const float4*>(src + (size_t)n * stride + c4 * 4));
        uint32_t h0, l0, h1, l1;
        bf_split2(v.x, v.y, h0, l0);
        bf_split2(v.z, v.w, h1, l1);
        uint32_t off = SWZ128((uint32_t)(n * 128 + c4 * 8));
        *reinterpret_cast<uint2*>(hi + off) = make_uint2(h0, h1);
        *reinterpret_cast<uint2*>(lo + off) = make_uint2(l0, l1);
    }
}

__device__ __forceinline__ void init_acc8(float (&acc)[2][8][4], const float* sBias, int e0)
{
#pragma unroll
    for (int mt = 0; mt < 2; mt++)
#pragma unroll
        for (int nt = 0; nt < 8; nt++) {
            float b0 = sBias[nt * 8 + e0], b1 = sBias[nt * 8 + e0 + 1];
            acc[mt][nt][0] = b0; acc[mt][nt][1] = b1;
            acc[mt][nt][2] = b0; acc[mt][nt][3] = b1;
        }
}
template<int NTS>
__device__ __forceinline__ void init_acc4(float (&acc)[2][4][4], const float* sBias,
                                          int e0, int nt0)
{
#pragma unroll
    for (int mt = 0; mt < 2; mt++)
#pragma unroll
        for (int nt = 0; nt < NTS; nt++) {
            float b0 = sBias[(nt0 + nt) * 8 + e0], b1 = sBias[(nt0 + nt) * 8 + e0 + 1];
            acc[mt][nt][0] = b0; acc[mt][nt][1] = b1;
            acc[mt][nt][2] = b0; acc[mt][nt][3] = b1;
        }
}

#define LGSCALE 0.721347520444482f
#define SQVF    0.044721359549996f

// ---------------- K1T: trunk on tensor cores, 256 threads (8 warps, N-split) ----------------
#define K1_XA_HI 0
#define K1_XA_LO 16384
#define K1_XB_HI 32768
#define K1_XB_LO 49152
#define K1_H_HI  65536
#define K1_H_LO  81920
#define K1_B0_HI 98304
#define K1_B0_LO 106496
#define K1_B1_HI 114688
#define K1_B1_LO 122880
#define K1_SR    131072
#define K1_SZ    164864
#define K1_SBIAS 198656
#define K1_SMEM  199168

__global__ void __launch_bounds__(256) k1t_trunk(
    const float* __restrict__ inp, const float* __restrict__ h0in,
    const float* __restrict__ fc1_w, const float* __restrict__ fc1_b,
    const float* __restrict__ wih, const float* __restrict__ whh,
    const float* __restrict__ bih, const float* __restrict__ bhh,
    const float* __restrict__ fc2_w, const float* __restrict__ fc2_b,
    const float* __restrict__ emb_w1, const float* __restrict__ emb_b1,
    const float* __restrict__ wq_w, const float* __restrict__ wq_b,
    const float* __restrict__ msg_w1, const float* __restrict__ msg_b1,
    float* __restrict__ h_out)
{
    extern __shared__ char sm[];
    const uint32_t sbase = smem_u32(sm);
    float* smf = reinterpret_cast<float*>(sm);
    float* sBias = smf + K1_SBIAS / 4;
    const int tid = threadIdx.x;
    const int wm = (tid >> 5) & 3;     // row-block
    const int wn = tid >> 7;           // N-half (0/1)
    const int nt0 = wn * 4;
    const int lane = tid & 31;
    const int e0 = 2 * (lane & 3);
    const int row0 = blockIdx.x * 128;
    const float qs = 0.17677669529663687f;

    // ---- A build: 2 threads per row split the k range ----
    {
        const int r = tid & 127;
        const int kh = tid >> 7;
        const float4* ip = reinterpret_cast<const float4*>(inp + (size_t)(row0 + r) * IND);
#pragma unroll
        for (int kk = 0; kk < 12; kk++) {
            int k = kh * 12 + kk;
            float4 v = __ldg(ip + k);
            uint32_t hA, lA, hB, lB;
            bf_split2(v.x, v.y, hA, lA);
            bf_split2(v.z, v.w, hB, lB);
            if (k < 16) {
                uint32_t off = SWZ128((uint32_t)(r * 128 + k * 8));
                *reinterpret_cast<uint2*>(sm + K1_XA_HI + off) = make_uint2(hA, hB);
                *reinterpret_cast<uint2*>(sm + K1_XA_LO + off) = make_uint2(lA, lB);
            } else {
                uint32_t off = SWZ128((uint32_t)(r * 128 + (k - 16) * 8));
                *reinterpret_cast<uint2*>(sm + K1_XB_HI + off) = make_uint2(hA, hB);
                *reinterpret_cast<uint2*>(sm + K1_XB_LO + off) = make_uint2(lA, lB);
            }
        }
        const float4* hp = reinterpret_cast<const float4*>(h0in + (size_t)(row0 + r) * HDIM);
#pragma unroll
        for (int kk = 0; kk < 8; kk++) {
            int k = kh * 8 + kk;
            float4 v = __ldg(hp + k);
            uint32_t hA, lA, hB, lB;
            bf_split2(v.x, v.y, hA, lA);
            bf_split2(v.z, v.w, hB, lB);
            uint32_t off = SWZ128((uint32_t)(r * 128 + k * 8));
            *reinterpret_cast<uint2*>(sm + K1_H_HI + off) = make_uint2(hA, hB);
            *reinterpret_cast<uint2*>(sm + K1_H_LO + off) = make_uint2(lA, lB);
        }
    }
    build_b64_256(sm + K1_B0_HI, sm + K1_B0_LO, fc1_w, IND, tid);
#pragma unroll
    for (int k = 0; k < 2; k++) {
        int idx = tid + k * 256;
        int n = idx >> 3, c4 = idx & 7;
        float4 v = __ldg(reinterpret_cast<const float4*>(fc1_w + (size_t)n * IND + 64 + c4 * 4));
        uint32_t h0_, l0_, h1_, l1_;
        bf_split2(v.x, v.y, h0_, l0_);
        bf_split2(v.z, v.w, h1_, l1_);
        uint32_t off = SWZ128((uint32_t)(n * 128 + c4 * 8));
        *reinterpret_cast<uint2*>(sm + K1_B1_HI + off) = make_uint2(h0_, h1_);
        *reinterpret_cast<uint2*>(sm + K1_B1_LO + off) = make_uint2(l0_, l1_);
    }
    if (tid < 64) sBias[tid] = __ldg(fc1_b + tid);
    __syncthreads();

    float acc[2][4][4];

    // ---- fc1 GEMM + relu -> x tile ----
    init_acc4<4>(acc, sBias, e0, nt0);
    mma_pass2<4, 4>(acc, sbase + K1_XA_HI, sbase + K1_XA_LO, sbase + K1_B0_HI, sbase + K1_B0_LO, wm, lane, nt0);
    mma_pass2<2, 4>(acc, sbase + K1_XB_HI, sbase + K1_XB_LO, sbase + K1_B1_HI, sbase + K1_B1_LO, wm, lane, nt0);
    __syncthreads();   // all MMAs done before XA overwrite
#pragma unroll
    for (int mt = 0; mt < 2; mt++)
#pragma unroll
        for (int h01 = 0; h01 < 2; h01++) {
            int row = wm * 32 + mt * 16 + (lane >> 2) + 8 * h01;
#pragma unroll
            for (int nt = 0; nt < 4; nt++) {
                int c = (nt0 + nt) * 8 + e0;
                float v0 = fmaxf(acc[mt][nt][h01 * 2 + 0], 0.f);
                float v1 = fmaxf(acc[mt][nt][h01 * 2 + 1], 0.f);
                uint32_t hh, ll;
                bf_split2(v0, v1, hh, ll);
                uint32_t off = SWZ128((uint32_t)(row * 128 + c * 2));
                *reinterpret_cast<uint32_t*>(sm + K1_XA_HI + off) = hh;
                *reinterpret_cast<uint32_t*>(sm + K1_XA_LO + off) = ll;
            }
        }
    __syncthreads();

    // ---- GRU r gate ----
    build_b64_256(sm + K1_B0_HI, sm + K1_B0_LO, wih, HDIM, tid);
    build_b64_256(sm + K1_B1_HI, sm + K1_B1_LO, whh, HDIM, tid);
    if (tid < 64) sBias[tid] = __ldg(bih + tid) + __ldg(bhh + tid);
    __syncthreads();
    init_acc4<4>(acc, sBias, e0, nt0);
    mma_pass2<4, 4>(acc, sbase + K1_XA_HI, sbase + K1_XA_LO, sbase + K1_B0_HI, sbase + K1_B0_LO, wm, lane, nt0);
    mma_pass2<4, 4>(acc, sbase + K1_H_HI,  sbase + K1_H_LO,  sbase + K1_B1_HI, sbase + K1_B1_LO, wm, lane, nt0);
#pragma unroll
    for (int mt = 0; mt < 2; mt++)
#pragma unroll
        for (int h01 = 0; h01 < 2; h01++) {
            int row = wm * 32 + mt * 16 + (lane >> 2) + 8 * h01;
#pragma unroll
            for (int nt = 0; nt < 4; nt++) {
                int c = (nt0 + nt) * 8 + e0;
                *reinterpret_cast<float2*>(smf + K1_SR / 4 + row * 66 + c) =
                    make_float2(sigmoidf_(acc[mt][nt][h01 * 2 + 0]),
                                sigmoidf_(acc[mt][nt][h01 * 2 + 1]));
            }
        }
    __syncthreads();

    // ---- GRU z gate ----
    build_b64_256(sm + K1_B0_HI, sm + K1_B0_LO, wih + 64 * HDIM, HDIM, tid);
    build_b64_256(sm + K1_B1_HI, sm + K1_B1_LO, whh + 64 * HDIM, HDIM, tid);
    if (tid < 64) sBias[tid] = __ldg(bih + 64 + tid) + __ldg(bhh + 64 + tid);
    __syncthreads();
    init_acc4<4>(acc, sBias, e0, nt0);
    mma_pass2<4, 4>(acc, sbase + K1_XA_HI, sbase + K1_XA_LO, sbase + K1_B0_HI, sbase + K1_B0_LO, wm, lane, nt0);
    mma_pass2<4, 4>(acc, sbase + K1_H_HI,  sbase + K1_H_LO,  sbase + K1_B1_HI, sbase + K1_B1_LO, wm, lane, nt0);
#pragma unroll
    for (int mt = 0; mt < 2; mt++)
#pragma unroll
        for (int h01 = 0; h01 < 2; h01++) {
            int row = wm * 32 + mt * 16 + (lane >> 2) + 8 * h01;
#pragma unroll
            for (int nt = 0; nt < 4; nt++) {
                int c = (nt0 + nt) * 8 + e0;
                *reinterpret_cast<float2*>(smf + K1_SZ / 4 + row * 66 + c) =
                    make_float2(sigmoidf_(acc[mt][nt][h01 * 2 + 0]),
                                sigmoidf_(acc[mt][nt][h01 * 2 + 1]));
            }
        }
    __syncthreads();

    // ---- GRU n gate ----
    build_b64_256(sm + K1_B0_HI, sm + K1_B0_LO, wih + 128 * HDIM, HDIM, tid);
    build_b64_256(sm + K1_B1_HI, sm + K1_B1_LO, whh + 128 * HDIM, HDIM, tid);
    if (tid < 64) sBias[tid] = __ldg(bih + 128 + tid);
    else if (tid < 128) sBias[tid] = __ldg(bhh + 128 + (tid - 64));
    __syncthreads();
    float acc2[2][4][4];
    init_acc4<4>(acc, sBias, e0, nt0);
    init_acc4<4>(acc2, sBias + 64, e0, nt0);
    mma_pass2<4, 4>(acc,  sbase + K1_XA_HI, sbase + K1_XA_LO, sbase + K1_B0_HI, sbase + K1_B0_LO, wm, lane, nt0);
    mma_pass2<4, 4>(acc2, sbase + K1_H_HI,  sbase + K1_H_LO,  sbase + K1_B1_HI, sbase + K1_B1_LO, wm, lane, nt0);
    __syncthreads();   // H-tile reads done before overwrite below

    // ---- blend ----
#pragma unroll
    for (int mt = 0; mt < 2; mt++)
#pragma unroll
        for (int h01 = 0; h01 < 2; h01++) {
            int row = wm * 32 + mt * 16 + (lane >> 2) + 8 * h01;
            int grow = row0 + row;
#pragma unroll
            for (int nt = 0; nt < 4; nt++) {
                int c = (nt0 + nt) * 8 + e0;
                float2 rv = *reinterpret_cast<const float2*>(smf + K1_SR / 4 + row * 66 + c);
                float2 zv = *reinterpret_cast<const float2*>(smf + K1_SZ / 4 + row * 66 + c);
                float n0 = tanhf(acc[mt][nt][h01 * 2 + 0] + rv.x * acc2[mt][nt][h01 * 2 + 0]);
                float n1 = tanhf(acc[mt][nt][h01 * 2 + 1] + rv.y * acc2[mt][nt][h01 * 2 + 1]);
                float2 h0v = __ldg(reinterpret_cast<const float2*>(h0in + (size_t)grow * HDIM + c));
                float hn0 = (1.f - zv.x) * n0 + zv.x * h0v.x;
                float hn1 = (1.f - zv.y) * n1 + zv.y * h0v.y;
                *reinterpret_cast<float2*>(h_out + (size_t)grow * HDIM + c) = make_float2(hn0, hn1);
                uint32_t hh, ll;
                bf_split2(hn0, hn1, hh, ll);
                uint32_t off = SWZ128((uint32_t)(row * 128 + c * 2));
                *reinterpret_cast<uint32_t*>(sm + K1_H_HI + off) = hh;
                *reinterpret_cast<uint32_t*>(sm + K1_H_LO + off) = ll;
            }
        }
    __syncthreads();

    // ---- heads ----
#pragma unroll
    for (int p = 0; p < 3; p++) {
        const int rows = (p == 2) ? 48 : 64;
#pragma unroll
        for (int k = 0; k < 4; k++) {
            int idx4 = tid + k * 256;
            int n = idx4 >> 4, c4 = idx4 & 15;
            if (n < rows) {
                int g = p * 64 + n;
                const float* src; float sc = 1.f;
                if (g < 16)       src = fc2_w + (size_t)g * HDIM;
                else if (g < 80)  src = emb_w1 + (size_t)(g - 16) * HDIM;
                else if (g < 112) { src = wq_w + (size_t)(g - 80) * HDIM; sc = qs; }
                else              src = msg_w1 + (size_t)(g - 112) * 80;
                float4 v = __ldg(reinterpret_cast<const float4*>(src + c4 * 4));
                uint32_t h0_, l0_, h1_, l1_;
                bf_split2(v.x * sc, v.y * sc, h0_, l0_);
                bf_split2(v.z * sc, v.w * sc, h1_, l1_);
                uint32_t off = SWZ128((uint32_t)(n * 128 + c4 * 8));
                *reinterpret_cast<uint2*>(sm + K1_B0_HI + off) = make_uint2(h0_, h1_);
                *reinterpret_cast<uint2*>(sm + K1_B0_LO + off) = make_uint2(l0_, l1_);
            }
        }
        if (tid < rows) {
            int g = p * 64 + tid; float bv;
            if (g < 16)       bv = __ldg(fc2_b + g);
            else if (g < 80)  bv = __ldg(emb_b1 + g - 16);
            else if (g < 112) bv = __ldg(wq_b + g - 80) * qs;
            else              bv = __ldg(msg_b1 + g - 112);
            sBias[tid] = bv;
        }
        __syncthreads();
        // warp's tile span for this head pass
        int myNts = 4;
        if (p == 2 && wn == 1) myNts = 2;
        if (myNts == 4) {
            init_acc4<4>(acc, sBias, e0, nt0);
            mma_pass2<4, 4>(acc, sbase + K1_H_HI, sbase + K1_H_LO, sbase + K1_B0_HI, sbase + K1_B0_LO, wm, lane, nt0);
        } else {
            init_acc4<2>(acc, sBias, e0, nt0);
            mma_pass2<4, 2>(acc, sbase + K1_H_HI, sbase + K1_H_LO, sbase + K1_B0_HI, sbase + K1_B0_LO, wm, lane, nt0);
        }
#pragma unroll
        for (int mt = 0; mt < 2; mt++)
#pragma unroll
            for (int h01 = 0; h01 < 2; h01++) {
                int row = wm * 32 + mt * 16 + (lane >> 2) + 8 * h01;
                int grow = row0 + row;
                for (int nt = 0; nt < myNts; nt++) {
                    int cg = p * 64 + (nt0 + nt) * 8 + e0;
                    float v0 = acc[mt][nt][h01 * 2 + 0];
                    float v1 = acc[mt][nt][h01 * 2 + 1];
                    float* dst;
                    if (cg < 16)       dst = g_q + (size_t)grow * NACTD + cg;
                    else if (cg < 80)  dst = g_z1 + (size_t)grow * NNHD + (cg - 16);
                    else if (cg < 112) dst = g_query + (size_t)grow * ATTD + (cg - 80);
                    else               dst = g_m1h + (size_t)grow * NNHD + (cg - 112);
                    *reinterpret_cast<float2*>(dst) = make_float2(v0, v1);
                }
            }
        __syncthreads();
    }
}

// ---------------- K2a/K2b: BN statistics ----------------
__global__ void __launch_bounds__(256) k2a_bn()
{
    __shared__ float ss[4][NNHD], sq[4][NNHD];
    const int tid = threadIdx.x;
    const int f = tid & 63;
    const int rg = tid >> 6;
    const int base = blockIdx.x * 256;
    float s = 0.f, q = 0.f;
    for (int r = rg; r < 256; r += 4) {
        float v = g_z1[(size_t)(base + r) * NNHD + f];
        s += v; q += v * v;
    }
    ss[rg][f] = s; sq[rg][f] = q;
    __syncthreads();
    if (tid < NNHD) {
        g_p1[blockIdx.x * NNHD + tid] = ss[0][tid] + ss[1][tid] + ss[2][tid] + ss[3][tid];
        g_p2[blockIdx.x * NNHD + tid] = sq[0][tid] + sq[1][tid] + sq[2][tid] + sq[3][tid];
    }
}
__global__ void __launch_bounds__(256) k2b_bn(const float* __restrict__ bn_g,
                                              const float* __restrict__ bn_b)
{
    __shared__ float ss[256], sq[256];
    const int tid = threadIdx.x;
    const int f = tid & 63;
    const int rg = tid >> 6;
    float s = 0.f, q = 0.f;
#pragma unroll
    for (int i = rg; i < 128; i += 4) {
        s += g_p1[i * NNHD + f];
        q += g_p2[i * NNHD + f];
    }
    ss[tid] = s; sq[tid] = q;
    __syncthreads();
    if (tid < NNHD) {
        float S = ss[f] + ss[64 + f] + ss[128 + f] + ss[192 + f];
        float Q = sq[f] + sq[64 + f] + sq[128 + f] + sq[192 + f];
        float mean = S * (1.f / (float)NROWS);
        float var  = Q * (1.f / (float)NROWS) - mean * mean;
        float a = __ldg(bn_g + f) / sqrtf(var + 1e-5f);
        g_bn_a[f] = a;
        g_bn_c[f] = __ldg(bn_b + f) - a * mean;
    }
}

// ---------------- K3m: latent GEMM (exact R10 form) ----------------
#define K3M_SA_HI 0
#define K3M_SA_LO 16384
#define K3M_SB_HI 32768
#define K3M_SB_LO 49152
#define K3M_SQK   65536
#define K3M_SQB   73728
#define K3M_SWK   74240
#define K3M_SBIAS 76288
#define K3M_SMEM  76800

__global__ void __launch_bounds__(128) k3m_latent(
    const float* __restrict__ eps,
    const float* __restrict__ emb_w2, const float* __restrict__ emb_b2,
    const float* __restrict__ wk_w, const float* __restrict__ wk_b)
{
    extern __shared__ char sm[];
    const uint32_t sbase = smem_u32(sm);
    float* smf = reinterpret_cast<float*>(sm);
    const int tid = threadIdx.x;
    const int w = tid >> 5;
    const int lane = tid & 31;
    const int row0 = blockIdx.x * 128;
    const int b = blockIdx.x * 4 + w;
    const int e0 = 2 * (lane & 3);

    {
        const float4* zpg = reinterpret_cast<const float4*>(g_z1 + (size_t)(row0 + tid) * NNHD);
#pragma unroll
        for (int k = 0; k < 16; k++) {
            float4 v = __ldg(zpg + k);
            float t0 = g_bn_a[4*k+0] * v.x + g_bn_c[4*k+0]; t0 = t0 > 0.f ? t0 : 0.01f * t0;
            float t1 = g_bn_a[4*k+1] * v.y + g_bn_c[4*k+1]; t1 = t1 > 0.f ? t1 : 0.01f * t1;
            float t2 = g_bn_a[4*k+2] * v.z + g_bn_c[4*k+2]; t2 = t2 > 0.f ? t2 : 0.01f * t2;
            float t3 = g_bn_a[4*k+3] * v.w + g_bn_c[4*k+3]; t3 = t3 > 0.f ? t3 : 0.01f * t3;
            uint32_t h0, l0, h1, l1;
            bf_split2(t0, t1, h0, l0);
            bf_split2(t2, t3, h1, l1);
            uint32_t off = SWZ128((uint32_t)(tid * 128 + k * 8));
            *reinterpret_cast<uint2*>(sm + K3M_SA_HI + off) = make_uint2(h0, h1);
            *reinterpret_cast<uint2*>(sm + K3M_SA_LO + off) = make_uint2(l0, l1);
        }
    }
    cload(smf + K3M_SWK / 4, wk_w, 128, tid, 128);
    __syncthreads();

    {
        const float* swk = smf + K3M_SWK / 4;
        float qk[16];
#pragma unroll
        for (int l = 0; l < 16; l++) qk[l] = 0.f;
        float qb = 0.f;
        const float4* qp = reinterpret_cast<const float4*>(g_query + (size_t)(row0 + tid) * ATTD);
#pragma unroll
        for (int k = 0; k < 8; k++) {
            float4 v = __ldg(qp + k);
            float qa[4] = {v.x, v.y, v.z, v.w};
#pragma unroll
            for (int u = 0; u < 4; u++) {
                int a = 4*k + u;
#pragma unroll
                for (int l = 0; l < 16; l++) qk[l] = fmaf(qa[u], swk[a*16 + l], qk[l]);
                qb = fmaf(qa[u], __ldg(wk_b + a), qb);
            }
        }
#pragma unroll
        for (int l = 0; l < 16; l++) smf[K3M_SQK / 4 + tid * 16 + l] = qk[l];
        smf[K3M_SQB / 4 + tid] = qb;
    }
    __syncthreads();

    float qkr[4][4], qbr[4];
#pragma unroll
    for (int rr = 0; rr < 4; rr++) {
        int rloc = w * 32 + ((rr >> 1) ? 16 : 0) + (lane >> 2) + ((rr & 1) ? 8 : 0);
        const float* q = smf + K3M_SQK / 4 + rloc * 16;
        qkr[rr][0] = q[e0]; qkr[rr][1] = q[e0 + 1];
        qkr[rr][2] = q[e0 + 8]; qkr[rr][3] = q[e0 + 9];
        qbr[rr] = smf[K3M_SQB / 4 + rloc];
    }

    for (int t = 0; t < 8; t++) {
        if (t > 0) __syncthreads();
#pragma unroll
        for (int k = 0; k < 16; k++) {
            int idx4 = tid + k * 128;
            int n = idx4 >> 4, c4 = idx4 & 15;
            int h = n >> 6, q = (n >> 5) & 1;
            int dl = 32 * h + (n & 31);
            int wrow = (q ? 512 : 0) + 64 * t + dl;
            float sc = q ? LGSCALE : 1.f;
            float4 v = __ldg(reinterpret_cast<const float4*>(emb_w2 + wrow * 64 + c4 * 4));
            uint32_t h0, l0, h1, l1;
            bf_split2(v.x * sc, v.y * sc, h0, l0);
            bf_split2(v.z * sc, v.w * sc, h1, l1);
            uint32_t off = SWZ128((uint32_t)(n * 128 + c4 * 8));
            *reinterpret_cast<uint2*>(sm + K3M_SB_HI + off) = make_uint2(h0, h1);
            *reinterpret_cast<uint2*>(sm + K3M_SB_LO + off) = make_uint2(l0, l1);
        }
        {
            int n = tid;
            int h = n >> 6, q = (n >> 5) & 1;
            int dl = 32 * h + (n & 31);
            float bv = __ldg(emb_b2 + (q ? 512 : 0) + 64 * t + dl);
            smf[K3M_SBIAS / 4 + n] = q ? bv * LGSCALE : bv;
        }
        __syncthreads();

        for (int hh = 0; hh < 2; hh++) {
            const int nbase = hh * 64;
            float acc[2][8][4];
            init_acc8(acc, smf + K3M_SBIAS / 4 + nbase, e0);
#pragma unroll
            for (int kt = 0; kt < 4; kt++) {
                uint32_t ah[2][4], al[2][4];
#pragma unroll
                for (int mt = 0; mt < 2; mt++) {
                    uint32_t aoff = SWZ128((uint32_t)(
                        (w * 32 + mt * 16 + (lane & 15)) * 128 + kt * 32 + (lane >> 4) * 16));
                    ldsm_x4(ah[mt][0], ah[mt][1], ah[mt][2], ah[mt][3], sbase + K3M_SA_HI + aoff);
                    ldsm_x4(al[mt][0], al[mt][1], al[mt][2], al[mt][3], sbase + K3M_SA_LO + aoff);
                }
#pragma unroll
                for (int nt = 0; nt < 8; nt++) {
                    uint32_t boff = SWZ128((uint32_t)(
                        (nbase + nt * 8 + (lane & 7)) * 128 + kt * 32 + ((lane >> 3) & 1) * 16));
                    uint32_t bh0, bh1, bl0, bl1;
                    ldsm_x2(bh0, bh1, sbase + K3M_SB_HI + boff);
                    ldsm_x2(bl0, bl1, sbase + K3M_SB_LO + boff);
#pragma unroll
                    for (int mt = 0; mt < 2; mt++) {
                        mma16816(acc[mt][nt], ah[mt], bh0, bh1);
                        mma16816(acc[mt][nt], ah[mt], bl0, bl1);
                        mma16816(acc[mt][nt], al[mt], bh0, bh1);
                    }
                }
            }
#pragma unroll
            for (int mt = 0; mt < 2; mt++) {
#pragma unroll
                for (int h01 = 0; h01 < 2; h01++) {
                    const int rloc = w * 32 + mt * 16 + (lane >> 2) + 8 * h01;
                    const int rr = mt * 2 + h01;
                    const int i = rloc & 31;
                    float ap0 = 0.f, ap1 = 0.f;
#pragma unroll
                    for (int nt = 0; nt < 4; nt++) {
                        const int c = nt * 8 + e0;
                        float mu0 = acc[mt][nt][h01*2+0];
                        float mu1 = acc[mt][nt][h01*2+1];
                        float lg0 = acc[mt][nt+4][h01*2+0];
                        float lg1 = acc[mt][nt+4][h01*2+1];
                        float s0 = fmaxf(exp2f(lg0), SQVF);
                        float s1 = fmaxf(exp2f(lg1), SQVF);
                        const int dglob = t * 64 + 32 * hh + c;
                        float2 ev = __ldg(reinterpret_cast<const float2*>(
                            eps + (size_t)(row0 + rloc) * DLAT + dglob));
                        float l0 = fmaf(s0, ev.x, mu0);
                        float l1 = fmaf(s1, ev.y, mu1);
                        const int j = 4 * t + 2 * hh + (c >> 4);
                        const int pos = c & 15;
                        *reinterpret_cast<float2*>(
                            g_lat + (((size_t)(b * AGN + j)) * AGN + i) * LDIM + pos)
                            = make_float2(l0, l1);
                        float pa = qkr[rr][(nt & 1) * 2 + 0] * l0
                                 + qkr[rr][(nt & 1) * 2 + 1] * l1;
                        if (nt < 2) ap0 += pa; else ap1 += pa;
                    }
                    ap0 += __shfl_xor_sync(0xffffffffu, ap0, 1);
                    ap0 += __shfl_xor_sync(0xffffffffu, ap0, 2);
                    ap1 += __shfl_xor_sync(0xffffffffu, ap1, 1);
                    ap1 += __shfl_xor_sync(0xffffffffu, ap1, 2);
                    if ((lane & 3) == 0) {
                        int j0 = 4 * t + 2 * hh;
                        g_alpha[((size_t)(b * AGN + j0)) * AGN + i]     = ap0 + qbr[rr];
                        g_alpha[((size_t)(b * AGN + j0 + 1)) * AGN + i] = ap1 + qbr[rr];
                    }
                }
            }
        }
    }
}

// ---------------- K4: softmax + message MLP + aggregate (R10 version) ----------------
#define K4_SMEM ((16384 + 16 * 68 + 16 + 32 * 33 + 8 * 68) * 4)
__global__ void __launch_bounds__(256) k4_msg(
    const float* __restrict__ msg_w1,
    const float* __restrict__ msg_w2, const float* __restrict__ msg_b2,
    float* __restrict__ ret_q)
{
    extern __shared__ float sm4[];
    float* latS = sm4;
    float* sW2  = sm4 + 16384;
    float* sB2  = sW2 + 16 * 68;
    float* sal  = sB2 + 16;
    float* sU   = sal + 32 * 33;
    const int tid = threadIdx.x;
    const int w = tid >> 5;
    const int lane = tid & 31;
    const int b = blockIdx.x;

    {
        const float4* latg = reinterpret_cast<const float4*>(g_lat + (size_t)b * 16384);
        float4* latd = reinterpret_cast<float4*>(latS);
#pragma unroll
        for (int i = 0; i < 16; i++)
            latd[tid + i * 256] = __ldg(latg + tid + i * 256);
    }
    for (int idx = tid; idx < 16 * 64; idx += 256) {
        int rr = idx >> 6, cc = idx & 63;
        sW2[rr * 68 + cc] = __ldg(msg_w2 + idx);
    }
    if (tid < 16) sB2[tid] = __ldg(msg_b2 + tid);
    for (int idx = tid; idx < 1024; idx += 256) {
        int jj = idx >> 5, ii = idx & 31;
        sal[jj * 33 + ii] = g_alpha[(size_t)b * 1024 + idx];
    }

    u64 w1a[8], w1b[8];
    {
        const float4* p0 = reinterpret_cast<const float4*>(msg_w1 + lane * 80 + 64);
        const float4* p1 = reinterpret_cast<const float4*>(msg_w1 + (lane + 32) * 80 + 64);
#pragma unroll
        for (int k = 0; k < 4; k++) {
            float4 v0 = __ldg(p0 + k), v1 = __ldg(p1 + k);
            w1a[2*k] = pk2(v0.x, v0.y); w1a[2*k+1] = pk2(v0.z, v0.w);
            w1b[2*k] = pk2(v1.x, v1.y); w1b[2*k+1] = pk2(v1.z, v1.w);
        }
    }
    __syncthreads();

    if (tid < 32) {
        const int ii = tid;
        float m = -3.4e38f;
#pragma unroll
        for (int j = 0; j < AGN; j++) {
            float v = (j == ii) ? -1e9f : sal[j * 33 + ii];
            m = fmaxf(m, v);
        }
        float s = 0.f;
#pragma unroll
        for (int j = 0; j < AGN; j++) {
            float v = (j == ii) ? -1e9f : sal[j * 33 + ii];
            float e = expf(v - m);
            sal[j * 33 + ii] = e;
            s += e;
        }
        float inv = 1.f / s;
#pragma unroll
        for (int j = 0; j < AGN; j++) sal[j * 33 + ii] *= inv;
    }
    __syncthreads();

#pragma unroll
    for (int jj = 0; jj < 4; jj++) {
        const int j = w + jj * 8;
        const int bj = b * AGN + j;
        const float m0 = __ldg(g_m1h + (size_t)bj * NNHD + lane);
        const float m1 = __ldg(g_m1h + (size_t)bj * NNHD + 32 + lane);
        const float* latbase = latS + j * 512;
        const float* alb = sal + j * 33;
        float u0 = 0.f, u1 = 0.f, sa = 0.f;

        for (int i = 0; i < AGN; i++) {
            const ulonglong2* l2 = reinterpret_cast<const ulonglong2*>(latbase + i * LDIM);
            ulonglong2 p0 = l2[0], p1 = l2[1], p2 = l2[2], p3 = l2[3];
            u64 a0 = 0ull, a1 = 0ull, b0 = 0ull, b1 = 0ull;
            a0 = fma2_(w1a[0], p0.x, a0); a1 = fma2_(w1a[1], p0.y, a1);
            b0 = fma2_(w1b[0], p0.x, b0); b1 = fma2_(w1b[1], p0.y, b1);
            a0 = fma2_(w1a[2], p1.x, a0); a1 = fma2_(w1a[3], p1.y, a1);
            b0 = fma2_(w1b[2], p1.x, b0); b1 = fma2_(w1b[3], p1.y, b1);
            a0 = fma2_(w1a[4], p2.x, a0); a1 = fma2_(w1a[5], p2.y, a1);
            b0 = fma2_(w1b[4], p2.x, b0); b1 = fma2_(w1b[5], p2.y, b1);
            a0 = fma2_(w1a[6], p3.x, a0); a1 = fma2_(w1a[7], p3.y, a1);
            b0 = fma2_(w1b[6], p3.x, b0); b1 = fma2_(w1b[7], p3.y, b1);
            float r0,r1,r2,r3; upk2(r0,r1,a0); upk2(r2,r3,a1);
            float s0 = m0 + ((r0+r1)+(r2+r3));
            upk2(r0,r1,b0); upk2(r2,r3,b1);
            float s1 = m1 + ((r0+r1)+(r2+r3));
            s0 = s0 > 0.f ? s0 : 0.01f * s0;
            s1 = s1 > 0.f ? s1 : 0.01f * s1;
            float al = alb[i];
            sa += al;
            u0 = fmaf(al, s0, u0);
            u1 = fmaf(al, s1, u1);
        }
        sU[w * 68 + lane] = u0; sU[w * 68 + 32 + lane] = u1;
        __syncwarp();
        if (lane < 16) {
            float acc = __ldg(g_q + (size_t)bj * NACTD + lane) + sa * sB2[lane];
            const float* w2r = sW2 + lane * 68;
            const float* uv = sU + w * 68;
            float c0 = 0.f, c1 = 0.f;
#pragma unroll
            for (int o = 0; o < 64; o += 2) {
                c0 = fmaf(w2r[o],   uv[o],   c0);
                c1 = fmaf(w2r[o+1], uv[o+1], c1);
            }
            ret_q[(size_t)bj * NACTD + lane] = acc + c0 + c1;
        }
        __syncwarp();
    }
}

// ---------------- host launcher ----------------
extern "C" void kernel_launch(void* const* d_in, const int* in_sizes, int n_in,
                              void* d_out, int out_size)
{
    (void)in_sizes; (void)n_in; (void)out_size;
    const float* inputs  = (const float*)d_in[0];
    const float* hidden  = (const float*)d_in[1];
    const float* eps     = (const float*)d_in[2];
    const float* fc1_w   = (const float*)d_in[3];
    const float* fc1_b   = (const float*)d_in[4];
    const float* gru_wih = (const float*)d_in[5];
    const float* gru_whh = (const float*)d_in[6];
    const float* gru_bih = (const float*)d_in[7];
    const float* gru_bhh = (const float*)d_in[8];
    const float* fc2_w   = (const float*)d_in[9];
    const float* fc2_b   = (const float*)d_in[10];
    const float* emb_w1  = (const float*)d_in[11];
    const float* emb_b1  = (const float*)d_in[12];
    const float* bn_g    = (const float*)d_in[13];
    const float* bn_b    = (const float*)d_in[14];
    const float* emb_w2  = (const float*)d_in[15];
    const float* emb_b2  = (const float*)d_in[16];
    const float* msg_w1  = (const float*)d_in[17];
    const float* msg_b1  = (const float*)d_in[18];
    const float* msg_w2  = (const float*)d_in[19];
    const float* msg_b2  = (const float*)d_in[20];
    const float* wq_w    = (const float*)d_in[21];
    const float* wq_b    = (const float*)d_in[22];
    const float* wk_w    = (const float*)d_in[23];
    const float* wk_b    = (const float*)d_in[24];

    float* out   = (float*)d_out;
    float* ret_q = out;                          // [32768,16]
    float* h_out = out + (size_t)NROWS * NACTD;  // [32768,64]

    cudaFuncSetAttribute(k1t_trunk,  cudaFuncAttributeMaxDynamicSharedMemorySize, K1_SMEM);
    cudaFuncSetAttribute(k3m_latent, cudaFuncAttributeMaxDynamicSharedMemorySize, K3M_SMEM);
    cudaFuncSetAttribute(k4_msg,     cudaFuncAttributeMaxDynamicSharedMemorySize, K4_SMEM);

    k1t_trunk<<<NROWS / 128, 256, K1_SMEM>>>(
        inputs, hidden, fc1_w, fc1_b, gru_wih, gru_whh, gru_bih, gru_bhh,
        fc2_w, fc2_b, emb_w1, emb_b1, wq_w, wq_b, msg_w1, msg_b1, h_out);

    k2a_bn<<<128, 256>>>();
    k2b_bn<<<1, 256>>>(bn_g, bn_b);

    k3m_latent<<<NROWS / 128, 128, K3M_SMEM>>>(eps, emb_w2, emb_b2, wk_w, wk_b);

    k4_msg<<<BSZ, 256, K4_SMEM>>>(msg_w1, msg_w2, msg_b2, ret_q);
}